// round 1
// baseline (speedup 1.0000x reference)
#include <cuda_runtime.h>
#include <math.h>

// Problem constants
constexpr int D    = 1024;
constexpr int NB   = 4;
constexpr int L    = 2048;
constexpr int H    = 16;
constexpr int HD   = 64;
constexpr int MLP  = 4096;
constexpr int ROWS = NB * L;  // 8192

// ---------------- scratch (device globals; no allocation allowed) ----------
__device__ float g_tp[NB * 6 * D];                       // 96 KB
__device__ float g_h[(size_t)ROWS * D];                  // 32 MB
__device__ float g_qkv[(size_t)ROWS * 3 * D];            // 96 MB
__device__ float g_attno[(size_t)ROWS * D];              // 32 MB
__device__ float g_x1[(size_t)ROWS * D];                 // 32 MB
__device__ float g_mlp[(size_t)ROWS * MLP];              // 128 MB
__device__ float g_scores[(size_t)NB * H * L * L];       // 1 GiB

// ---------------- time embedding projection --------------------------------
// tp[b][j] = sum_k silu(te[b][k]) * Wt[k][j] + bt[j]
__global__ void time_proj_kernel(const float* __restrict__ te,
                                 const float* __restrict__ Wt,
                                 const float* __restrict__ bt) {
    __shared__ float s[D];
    int b   = blockIdx.y;
    int tid = threadIdx.x;
    for (int i = tid; i < D; i += 256) {
        float v = te[b * D + i];
        s[i] = v / (1.0f + expf(-v));
    }
    __syncthreads();
    int j = blockIdx.x * 256 + tid;
    float acc = bt[j];
#pragma unroll 8
    for (int k = 0; k < D; k++) acc = fmaf(s[k], Wt[(size_t)k * (6 * D) + j], acc);
    g_tp[b * 6 * D + j] = acc;
}

// ---------------- LayerNorm + AdaLN modulation ------------------------------
// out = LN(x)*g+be, then *(1+scale)+shift  (scale/shift from g_tp at offsets)
__global__ void ln_mod_kernel(const float* __restrict__ x,
                              const float* __restrict__ g,
                              const float* __restrict__ be,
                              float* __restrict__ out,
                              int shift_off, int scale_off) {
    int row = blockIdx.x;
    int b   = row / L;
    const float* xr = x + (size_t)row * D;
    int tid = threadIdx.x;
    float4 v = ((const float4*)xr)[tid];
    float s = v.x + v.y + v.z + v.w;
    float q = v.x * v.x + v.y * v.y + v.z * v.z + v.w * v.w;
#pragma unroll
    for (int o = 16; o; o >>= 1) {
        s += __shfl_xor_sync(0xffffffffu, s, o);
        q += __shfl_xor_sync(0xffffffffu, q, o);
    }
    __shared__ float ss[8], sq[8];
    __shared__ float s_mu, s_rs;
    int w = tid >> 5;
    if ((tid & 31) == 0) { ss[w] = s; sq[w] = q; }
    __syncthreads();
    if (tid == 0) {
        float S = 0.f, Q = 0.f;
        for (int i = 0; i < 8; i++) { S += ss[i]; Q += sq[i]; }
        float mu  = S / D;
        float var = Q / D - mu * mu;
        s_mu = mu;
        s_rs = rsqrtf(var + 1e-5f);
    }
    __syncthreads();
    float mu = s_mu, rs = s_rs;
    int j = tid * 4;
    const float* tpb = g_tp + b * 6 * D;
    float4 gv = ((const float4*)g)[tid];
    float4 bv = ((const float4*)be)[tid];
    float4 sc = *(const float4*)(tpb + scale_off + j);
    float4 sh = *(const float4*)(tpb + shift_off + j);
    float4 o;
    o.x = ((v.x - mu) * rs * gv.x + bv.x) * (1.0f + sc.x) + sh.x;
    o.y = ((v.y - mu) * rs * gv.y + bv.y) * (1.0f + sc.y) + sh.y;
    o.z = ((v.z - mu) * rs * gv.z + bv.z) * (1.0f + sc.z) + sh.z;
    o.w = ((v.w - mu) * rs * gv.w + bv.w) * (1.0f + sc.w) + sh.w;
    ((float4*)(out + (size_t)row * D))[tid] = o;
}

// ---------------- generic SGEMM: C = act(A@B + bias) [+ residual gate] ------
// EPI 0: bias only.  EPI 1: exact GELU.  EPI 2: res + gate*(acc+bias)
template <int EPI>
__global__ void __launch_bounds__(256) sgemm_kernel(
    const float* __restrict__ A, const float* __restrict__ Bm,
    const float* __restrict__ bias, const float* __restrict__ res,
    int gate_off, float* __restrict__ C, int M, int N, int K) {
    constexpr int BM = 128, BN = 128, BK = 8;
    __shared__ float As[BK][BM];
    __shared__ float Bs[BK][BN];
    int tid   = threadIdx.x;
    int a_row = tid >> 1;
    int a_col = (tid & 1) * 4;
    int b_row = tid >> 5;
    int b_col = (tid & 31) * 4;
    const float* Ap = A + (size_t)(blockIdx.y * BM + a_row) * K + a_col;
    const float* Bp = Bm + (size_t)b_row * N + blockIdx.x * BN + b_col;
    int tx = tid & 15, ty = tid >> 4;
    float acc[8][8];
#pragma unroll
    for (int i = 0; i < 8; i++)
#pragma unroll
        for (int j = 0; j < 8; j++) acc[i][j] = 0.0f;

    for (int k0 = 0; k0 < K; k0 += BK) {
        float4 av = *(const float4*)Ap; Ap += BK;
        float4 bv = *(const float4*)Bp; Bp += (size_t)BK * N;
        As[a_col + 0][a_row] = av.x;
        As[a_col + 1][a_row] = av.y;
        As[a_col + 2][a_row] = av.z;
        As[a_col + 3][a_row] = av.w;
        *(float4*)&Bs[b_row][b_col] = bv;
        __syncthreads();
#pragma unroll
        for (int k = 0; k < BK; k++) {
            float ra[8], rb[8];
            *(float4*)(ra)     = *(const float4*)&As[k][ty * 8];
            *(float4*)(ra + 4) = *(const float4*)&As[k][ty * 8 + 4];
            *(float4*)(rb)     = *(const float4*)&Bs[k][tx * 8];
            *(float4*)(rb + 4) = *(const float4*)&Bs[k][tx * 8 + 4];
#pragma unroll
            for (int i = 0; i < 8; i++)
#pragma unroll
                for (int j = 0; j < 8; j++) acc[i][j] = fmaf(ra[i], rb[j], acc[i][j]);
        }
        __syncthreads();
    }

    int m0 = blockIdx.y * BM + ty * 8;
    int n0 = blockIdx.x * BN + tx * 8;
    float bvals[8];
    *(float4*)bvals       = *(const float4*)(bias + n0);
    *(float4*)(bvals + 4) = *(const float4*)(bias + n0 + 4);
#pragma unroll
    for (int i = 0; i < 8; i++) {
        int m = m0 + i;
        float vout[8];
#pragma unroll
        for (int j = 0; j < 8; j++) {
            float v = acc[i][j] + bvals[j];
            if (EPI == 1) v = 0.5f * v * (1.0f + erff(v * 0.7071067811865475f));
            vout[j] = v;
        }
        if (EPI == 2) {
            int bb = m / L;
            const float* gp = g_tp + bb * 6 * D + gate_off + n0;
            const float* rp = res + (size_t)m * N + n0;
#pragma unroll
            for (int j = 0; j < 8; j++) vout[j] = rp[j] + gp[j] * vout[j];
        }
        float* cp = C + (size_t)m * N + n0;
        *(float4*)cp       = *(float4*)vout;
        *(float4*)(cp + 4) = *(float4*)(vout + 4);
    }
}

// ---------------- attention: scores = scale * Q K^T --------------------------
__global__ void __launch_bounds__(256) attn_qk_kernel() {
    // transposed smem tiles: [d][row], pad 65 to kill bank conflicts
    __shared__ float Qs[64][65];
    __shared__ float Ks[64][65];
    int bh = blockIdx.z;
    int b = bh >> 4, h = bh & 15;
    int mt = blockIdx.y, nt = blockIdx.x;
    int tid = threadIdx.x;
    const float* qbase = g_qkv + (size_t)(b * L) * (3 * D) + h * HD;
    for (int i = tid; i < 1024; i += 256) {
        int r = i >> 4, c = (i & 15) << 2;
        float4 qv = *(const float4*)(qbase + (size_t)(mt * 64 + r) * (3 * D) + c);
        Qs[c + 0][r] = qv.x; Qs[c + 1][r] = qv.y; Qs[c + 2][r] = qv.z; Qs[c + 3][r] = qv.w;
        float4 kv = *(const float4*)(qbase + D + (size_t)(nt * 64 + r) * (3 * D) + c);
        Ks[c + 0][r] = kv.x; Ks[c + 1][r] = kv.y; Ks[c + 2][r] = kv.z; Ks[c + 3][r] = kv.w;
    }
    __syncthreads();
    int tx = tid & 15, ty = tid >> 4;
    float acc[4][4] = {};
#pragma unroll 4
    for (int d = 0; d < 64; d++) {
        float qa[4], kb[4];
#pragma unroll
        for (int i = 0; i < 4; i++) qa[i] = Qs[d][ty * 4 + i];
#pragma unroll
        for (int j = 0; j < 4; j++) kb[j] = Ks[d][tx * 4 + j];
#pragma unroll
        for (int i = 0; i < 4; i++)
#pragma unroll
            for (int j = 0; j < 4; j++) acc[i][j] = fmaf(qa[i], kb[j], acc[i][j]);
    }
    const float scale = 0.125f;  // 1/sqrt(64)
    float* sbase = g_scores + ((size_t)bh * L + mt * 64 + ty * 4) * L + nt * 64 + tx * 4;
#pragma unroll
    for (int i = 0; i < 4; i++) {
        float4 o = make_float4(acc[i][0] * scale, acc[i][1] * scale,
                               acc[i][2] * scale, acc[i][3] * scale);
        *(float4*)(sbase + (size_t)i * L) = o;
    }
}

// ---------------- attention: row softmax (in place) --------------------------
__global__ void __launch_bounds__(256) softmax_kernel() {
    float* p = g_scores + (size_t)blockIdx.x * L;
    int tid = threadIdx.x;
    float4 v0 = ((const float4*)p)[tid * 2];
    float4 v1 = ((const float4*)p)[tid * 2 + 1];
    float m = fmaxf(fmaxf(fmaxf(v0.x, v0.y), fmaxf(v0.z, v0.w)),
                    fmaxf(fmaxf(v1.x, v1.y), fmaxf(v1.z, v1.w)));
#pragma unroll
    for (int o = 16; o; o >>= 1) m = fmaxf(m, __shfl_xor_sync(0xffffffffu, m, o));
    __shared__ float sred[8];
    __shared__ float s_bcast;
    int w = tid >> 5;
    if ((tid & 31) == 0) sred[w] = m;
    __syncthreads();
    if (tid == 0) {
        float mm = sred[0];
        for (int i = 1; i < 8; i++) mm = fmaxf(mm, sred[i]);
        s_bcast = mm;
    }
    __syncthreads();
    m = s_bcast;
    v0.x = expf(v0.x - m); v0.y = expf(v0.y - m); v0.z = expf(v0.z - m); v0.w = expf(v0.w - m);
    v1.x = expf(v1.x - m); v1.y = expf(v1.y - m); v1.z = expf(v1.z - m); v1.w = expf(v1.w - m);
    float s = v0.x + v0.y + v0.z + v0.w + v1.x + v1.y + v1.z + v1.w;
#pragma unroll
    for (int o = 16; o; o >>= 1) s += __shfl_xor_sync(0xffffffffu, s, o);
    __syncthreads();
    if ((tid & 31) == 0) sred[w] = s;
    __syncthreads();
    if (tid == 0) {
        float t = 0.f;
        for (int i = 0; i < 8; i++) t += sred[i];
        s_bcast = t;
    }
    __syncthreads();
    float inv = 1.0f / s_bcast;
    v0.x *= inv; v0.y *= inv; v0.z *= inv; v0.w *= inv;
    v1.x *= inv; v1.y *= inv; v1.z *= inv; v1.w *= inv;
    ((float4*)p)[tid * 2]     = v0;
    ((float4*)p)[tid * 2 + 1] = v1;
}

// ---------------- attention: out = P @ V -------------------------------------
__global__ void __launch_bounds__(256) attn_pv_kernel() {
    __shared__ float Ps[64][65];  // [m][k]
    __shared__ float Vs[64][64];  // [k][d]
    int bh = blockIdx.y;
    int b = bh >> 4, h = bh & 15;
    int mt = blockIdx.x;
    int tid = threadIdx.x;
    int tx = tid & 15, ty = tid >> 4;
    const float* vbase = g_qkv + (size_t)(b * L) * (3 * D) + 2 * D + h * HD;
    const float* pbase = g_scores + ((size_t)bh * L + mt * 64) * L;
    float acc[4][4] = {};
    for (int kt = 0; kt < L / 64; kt++) {
        for (int i = tid; i < 1024; i += 256) {
            int r = i >> 4, c = (i & 15) << 2;
            float4 pv = *(const float4*)(pbase + (size_t)r * L + kt * 64 + c);
            Ps[r][c + 0] = pv.x; Ps[r][c + 1] = pv.y; Ps[r][c + 2] = pv.z; Ps[r][c + 3] = pv.w;
            float4 vv = *(const float4*)(vbase + (size_t)(kt * 64 + r) * (3 * D) + c);
            *(float4*)&Vs[r][c] = vv;
        }
        __syncthreads();
#pragma unroll 4
        for (int k = 0; k < 64; k++) {
            float pa[4], vb[4];
#pragma unroll
            for (int i = 0; i < 4; i++) pa[i] = Ps[ty * 4 + i][k];
#pragma unroll
            for (int j = 0; j < 4; j++) vb[j] = Vs[k][tx * 4 + j];
#pragma unroll
            for (int i = 0; i < 4; i++)
#pragma unroll
                for (int j = 0; j < 4; j++) acc[i][j] = fmaf(pa[i], vb[j], acc[i][j]);
        }
        __syncthreads();
    }
    float* obase = g_attno + (size_t)(b * L + mt * 64 + ty * 4) * D + h * HD + tx * 4;
#pragma unroll
    for (int i = 0; i < 4; i++) {
        float4 o = make_float4(acc[i][0], acc[i][1], acc[i][2], acc[i][3]);
        *(float4*)(obase + (size_t)i * D) = o;
    }
}

// ---------------- launch ------------------------------------------------------
extern "C" void kernel_launch(void* const* d_in, const int* in_sizes, int n_in,
                              void* d_out, int out_size) {
    const float* x     = (const float*)d_in[0];
    const float* te    = (const float*)d_in[1];
    const float* Wqkv  = (const float*)d_in[2];
    const float* bqkv  = (const float*)d_in[3];
    const float* Wproj = (const float*)d_in[4];
    const float* bproj = (const float*)d_in[5];
    const float* W1    = (const float*)d_in[6];
    const float* b1    = (const float*)d_in[7];
    const float* W2    = (const float*)d_in[8];
    const float* b2    = (const float*)d_in[9];
    const float* Wt    = (const float*)d_in[10];
    const float* bt    = (const float*)d_in[11];
    const float* g1    = (const float*)d_in[12];
    const float* be1   = (const float*)d_in[13];
    const float* g2    = (const float*)d_in[14];
    const float* be2   = (const float*)d_in[15];
    float* out = (float*)d_out;

    float *p_h, *p_qkv, *p_attno, *p_x1, *p_mlp;
    cudaGetSymbolAddress((void**)&p_h, g_h);
    cudaGetSymbolAddress((void**)&p_qkv, g_qkv);
    cudaGetSymbolAddress((void**)&p_attno, g_attno);
    cudaGetSymbolAddress((void**)&p_x1, g_x1);
    cudaGetSymbolAddress((void**)&p_mlp, g_mlp);

    // 1. time modulation params
    time_proj_kernel<<<dim3(6 * D / 256, NB), 256>>>(te, Wt, bt);
    // 2. LN1 + msa modulation
    ln_mod_kernel<<<ROWS, 256>>>(x, g1, be1, p_h, 0, D);
    // 3. QKV projection
    sgemm_kernel<0><<<dim3(3 * D / 128, ROWS / 128), 256>>>(
        p_h, Wqkv, bqkv, nullptr, 0, p_qkv, ROWS, 3 * D, D);
    // 4. attention
    attn_qk_kernel<<<dim3(L / 64, L / 64, NB * H), 256>>>();
    softmax_kernel<<<NB * H * L, 256>>>();
    attn_pv_kernel<<<dim3(L / 64, NB * H), 256>>>();
    // 5. output projection + gated residual -> x1
    sgemm_kernel<2><<<dim3(D / 128, ROWS / 128), 256>>>(
        p_attno, Wproj, bproj, x, 2 * D, p_x1, ROWS, D, D);
    // 6. LN2 + mlp modulation
    ln_mod_kernel<<<ROWS, 256>>>(p_x1, g2, be2, p_h, 3 * D, 4 * D);
    // 7. MLP up + exact GELU
    sgemm_kernel<1><<<dim3(MLP / 128, ROWS / 128), 256>>>(
        p_h, W1, b1, nullptr, 0, p_mlp, ROWS, MLP, D);
    // 8. MLP down + gated residual -> output
    sgemm_kernel<2><<<dim3(D / 128, ROWS / 128), 256>>>(
        p_mlp, W2, b2, p_x1, 5 * D, out, ROWS, D, MLP);
}

// round 3
// speedup vs baseline: 1.3085x; 1.3085x over previous
#include <cuda_runtime.h>
#include <cuda_bf16.h>
#include <math.h>
#include <stdint.h>

// Problem constants
constexpr int D    = 1024;
constexpr int NB   = 4;
constexpr int L    = 2048;
constexpr int H    = 16;
constexpr int HD   = 64;
constexpr int MLP  = 4096;
constexpr int ROWS = NB * L;  // 8192

// ---------------- scratch (device globals; no allocation allowed) ----------
__device__ float g_tp[NB * 6 * D];
__device__ float g_h[(size_t)ROWS * D];
__device__ float g_qkv[(size_t)ROWS * 3 * D];
__device__ float g_attno[(size_t)ROWS * D];
__device__ float g_x1[(size_t)ROWS * D];
__device__ float g_mlp[(size_t)ROWS * MLP];
__device__ float g_scores[(size_t)NB * H * L * L];

// =================== helpers ==========================
__device__ __forceinline__ uint32_t smem_u32(const void* p) {
    uint32_t a;
    asm("{ .reg .u64 t; cvta.to.shared.u64 t, %1; cvt.u32.u64 %0, t; }"
        : "=r"(a) : "l"(p));
    return a;
}

// bf16 hi/lo split: (x,y) -> packed hi bf16x2, packed lo bf16x2
__device__ __forceinline__ void split2(float x, float y, uint32_t& hi, uint32_t& lo) {
    __nv_bfloat162 h = __floats2bfloat162_rn(x, y);
    float rx = __bfloat162float(h.x), ry = __bfloat162float(h.y);
    __nv_bfloat162 l = __floats2bfloat162_rn(x - rx, y - ry);
    hi = *reinterpret_cast<uint32_t*>(&h);
    lo = *reinterpret_cast<uint32_t*>(&l);
}

#define LDSM_X4(r0, r1, r2, r3, addr)                                          \
    asm volatile("ldmatrix.sync.aligned.m8n8.x4.shared.b16 {%0,%1,%2,%3}, [%4];" \
                 : "=r"(r0), "=r"(r1), "=r"(r2), "=r"(r3) : "r"(addr))
#define LDSM_X2(r0, r1, addr)                                                  \
    asm volatile("ldmatrix.sync.aligned.m8n8.x2.shared.b16 {%0,%1}, [%2];"     \
                 : "=r"(r0), "=r"(r1) : "r"(addr))
#define MMA_BF16(c, a, b)                                                      \
    asm volatile("mma.sync.aligned.m16n8k16.row.col.f32.bf16.bf16.f32 "        \
                 "{%0,%1,%2,%3}, {%4,%5,%6,%7}, {%8,%9}, {%0,%1,%2,%3};"       \
                 : "+f"((c)[0]), "+f"((c)[1]), "+f"((c)[2]), "+f"((c)[3])      \
                 : "r"((a)[0]), "r"((a)[1]), "r"((a)[2]), "r"((a)[3]),         \
                   "r"((b)[0]), "r"((b)[1]))

// ================== HMMA GEMM: C = epi(A @ W + bias) ======================
// A [M,K] fp32 row-major, W [K,N] fp32 row-major.
// 128x128 CTA tile, BK=32, 8 warps (4M x 2N), warp tile 32x64.
// bf16 hi/lo split: acc += Ah*Bh + Ah*Bl + Al*Bh  (~1e-5 rel accuracy).
// EPI 0: bias. EPI 1: exact GELU. EPI 2: res + gate * (acc + bias).
template <int EPI>
__global__ void __launch_bounds__(256, 1) hmma_gemm(
    const float* __restrict__ A, const float* __restrict__ W,
    const float* __restrict__ bias, const float* __restrict__ res,
    int gate_off, float* __restrict__ C, int N, int K) {
    // padded rows: 40 bf16 = 80 B = 5*16 B (ldmatrix-aligned, conflict-spread)
    __shared__ __align__(16) __nv_bfloat16 As_hi[128][40];
    __shared__ __align__(16) __nv_bfloat16 As_lo[128][40];
    __shared__ __align__(16) __nv_bfloat16 Bs_hi[128][40];
    __shared__ __align__(16) __nv_bfloat16 Bs_lo[128][40];

    const int tid  = threadIdx.x;
    const int lane = tid & 31;
    const int warp = tid >> 5;
    const int wm   = warp >> 1;  // 0..3
    const int wn   = warp & 1;   // 0..1
    const int m_base = blockIdx.y * 128;
    const int n_base = blockIdx.x * 128;

    float acc[2][8][4];
#pragma unroll
    for (int mi = 0; mi < 2; mi++)
#pragma unroll
        for (int ni = 0; ni < 8; ni++)
#pragma unroll
            for (int c = 0; c < 4; c++) acc[mi][ni][c] = 0.0f;

    // ldmatrix source addresses (fixed per thread; k-offset varies)
    // A: lane l -> row (l&15), k-col (l>>4)*8
    // B: lane l -> n-row (l&7), k-col ((l>>3)&1)*8
    const int a_row = lane & 15;
    const int a_kc  = (lane >> 4) * 8;
    const int b_row = lane & 7;
    const int b_kc  = ((lane >> 3) & 1) * 8;

    const int nblk = K >> 5;
    for (int blk = 0; blk < nblk; blk++) {
        const int k0 = blk << 5;
        // ---- load global -> regs ----
        float4 av[4];
        int ar4[4], ac4[4];
#pragma unroll
        for (int i = 0; i < 4; i++) {
            int idx = tid + 256 * i;          // 1024 float4 = 128 rows x 8
            ar4[i] = idx >> 3;
            ac4[i] = idx & 7;
            av[i] = *(const float4*)(A + (size_t)(m_base + ar4[i]) * K + k0 + ac4[i] * 4);
        }
        const int nb = tid & 31;              // n block (4 cols)
        const int kb = tid >> 5;              // k block (4 rows)
        const float* Wp = W + (size_t)(k0 + kb * 4) * N + n_base + nb * 4;
        float4 w0 = *(const float4*)(Wp);
        float4 w1 = *(const float4*)(Wp + (size_t)N);
        float4 w2 = *(const float4*)(Wp + 2 * (size_t)N);
        float4 w3 = *(const float4*)(Wp + 3 * (size_t)N);

        __syncthreads();  // previous compute done
        // ---- store regs -> smem (split hi/lo) ----
#pragma unroll
        for (int i = 0; i < 4; i++) {
            uint32_t h0, l0, h1, l1;
            split2(av[i].x, av[i].y, h0, l0);
            split2(av[i].z, av[i].w, h1, l1);
            *(uint2*)&As_hi[ar4[i]][ac4[i] * 4] = make_uint2(h0, h1);
            *(uint2*)&As_lo[ar4[i]][ac4[i] * 4] = make_uint2(l0, l1);
        }
        {
            float t[4][4] = {{w0.x, w1.x, w2.x, w3.x}, {w0.y, w1.y, w2.y, w3.y},
                             {w0.z, w1.z, w2.z, w3.z}, {w0.w, w1.w, w2.w, w3.w}};
#pragma unroll
            for (int i = 0; i < 4; i++) {
                uint32_t h0, l0, h1, l1;
                split2(t[i][0], t[i][1], h0, l0);
                split2(t[i][2], t[i][3], h1, l1);
                *(uint2*)&Bs_hi[nb * 4 + i][kb * 4] = make_uint2(h0, h1);
                *(uint2*)&Bs_lo[nb * 4 + i][kb * 4] = make_uint2(l0, l1);
            }
        }
        __syncthreads();
        // ---- compute: 2 k16 steps ----
#pragma unroll
        for (int ks = 0; ks < 2; ks++) {
            const int kc = ks * 16;
            uint32_t a_h[2][4], a_l[2][4];
#pragma unroll
            for (int mi = 0; mi < 2; mi++) {
                int r = wm * 32 + mi * 16 + a_row;
                LDSM_X4(a_h[mi][0], a_h[mi][1], a_h[mi][2], a_h[mi][3],
                        smem_u32(&As_hi[r][kc + a_kc]));
                LDSM_X4(a_l[mi][0], a_l[mi][1], a_l[mi][2], a_l[mi][3],
                        smem_u32(&As_lo[r][kc + a_kc]));
            }
#pragma unroll
            for (int ni = 0; ni < 8; ni++) {
                int nr = wn * 64 + ni * 8 + b_row;
                uint32_t b_h[2], b_l[2];
                LDSM_X2(b_h[0], b_h[1], smem_u32(&Bs_hi[nr][kc + b_kc]));
                LDSM_X2(b_l[0], b_l[1], smem_u32(&Bs_lo[nr][kc + b_kc]));
#pragma unroll
                for (int mi = 0; mi < 2; mi++) {
                    MMA_BF16(acc[mi][ni], a_h[mi], b_h);
                    MMA_BF16(acc[mi][ni], a_h[mi], b_l);
                    MMA_BF16(acc[mi][ni], a_l[mi], b_h);
                }
            }
        }
    }

    // ---- epilogue ----
    const int col_base = n_base + wn * 64 + (lane & 3) * 2;
    const int row_base = m_base + wm * 32 + (lane >> 2);
#pragma unroll
    for (int mi = 0; mi < 2; mi++) {
#pragma unroll
        for (int half = 0; half < 2; half++) {
            const int m = row_base + mi * 16 + half * 8;
            const int bb = m / L;
#pragma unroll
            for (int ni = 0; ni < 8; ni++) {
                const int col = col_base + ni * 8;
                float2 bv = *(const float2*)(bias + col);
                float vx = acc[mi][ni][half * 2 + 0] + bv.x;
                float vy = acc[mi][ni][half * 2 + 1] + bv.y;
                if (EPI == 1) {
                    vx = 0.5f * vx * (1.0f + erff(vx * 0.7071067811865475f));
                    vy = 0.5f * vy * (1.0f + erff(vy * 0.7071067811865475f));
                }
                if (EPI == 2) {
                    float2 gv = *(const float2*)(g_tp + bb * 6 * D + gate_off + col);
                    float2 rv = *(const float2*)(res + (size_t)m * N + col);
                    vx = rv.x + gv.x * vx;
                    vy = rv.y + gv.y * vy;
                }
                *(float2*)(C + (size_t)m * N + col) = make_float2(vx, vy);
            }
        }
    }
}

// ---------------- time embedding projection --------------------------------
__global__ void time_proj_kernel(const float* __restrict__ te,
                                 const float* __restrict__ Wt,
                                 const float* __restrict__ bt) {
    __shared__ float s[D];
    int b   = blockIdx.y;
    int tid = threadIdx.x;
    for (int i = tid; i < D; i += 256) {
        float v = te[b * D + i];
        s[i] = v / (1.0f + expf(-v));
    }
    __syncthreads();
    int j = blockIdx.x * 256 + tid;
    float acc = bt[j];
#pragma unroll 8
    for (int k = 0; k < D; k++) acc = fmaf(s[k], Wt[(size_t)k * (6 * D) + j], acc);
    g_tp[b * 6 * D + j] = acc;
}

// ---------------- LayerNorm + AdaLN modulation ------------------------------
__global__ void ln_mod_kernel(const float* __restrict__ x,
                              const float* __restrict__ g,
                              const float* __restrict__ be,
                              float* __restrict__ out,
                              int shift_off, int scale_off) {
    int row = blockIdx.x;
    int b   = row / L;
    const float* xr = x + (size_t)row * D;
    int tid = threadIdx.x;
    float4 v = ((const float4*)xr)[tid];
    float s = v.x + v.y + v.z + v.w;
    float q = v.x * v.x + v.y * v.y + v.z * v.z + v.w * v.w;
#pragma unroll
    for (int o = 16; o; o >>= 1) {
        s += __shfl_xor_sync(0xffffffffu, s, o);
        q += __shfl_xor_sync(0xffffffffu, q, o);
    }
    __shared__ float ss[8], sq[8];
    __shared__ float s_mu, s_rs;
    int w = tid >> 5;
    if ((tid & 31) == 0) { ss[w] = s; sq[w] = q; }
    __syncthreads();
    if (tid == 0) {
        float S = 0.f, Q = 0.f;
        for (int i = 0; i < 8; i++) { S += ss[i]; Q += sq[i]; }
        float mu  = S / D;
        float var = Q / D - mu * mu;
        s_mu = mu;
        s_rs = rsqrtf(var + 1e-5f);
    }
    __syncthreads();
    float mu = s_mu, rs = s_rs;
    int j = tid * 4;
    const float* tpb = g_tp + b * 6 * D;
    float4 gv = ((const float4*)g)[tid];
    float4 bv = ((const float4*)be)[tid];
    float4 sc = *(const float4*)(tpb + scale_off + j);
    float4 sh = *(const float4*)(tpb + shift_off + j);
    float4 o;
    o.x = ((v.x - mu) * rs * gv.x + bv.x) * (1.0f + sc.x) + sh.x;
    o.y = ((v.y - mu) * rs * gv.y + bv.y) * (1.0f + sc.y) + sh.y;
    o.z = ((v.z - mu) * rs * gv.z + bv.z) * (1.0f + sc.z) + sh.z;
    o.w = ((v.w - mu) * rs * gv.w + bv.w) * (1.0f + sc.w) + sh.w;
    ((float4*)(out + (size_t)row * D))[tid] = o;
}

// ---------------- attention: scores = scale * Q K^T --------------------------
__global__ void __launch_bounds__(256) attn_qk_kernel() {
    __shared__ float Qs[64][65];
    __shared__ float Ks[64][65];
    int bh = blockIdx.z;
    int b = bh >> 4, h = bh & 15;
    int mt = blockIdx.y, nt = blockIdx.x;
    int tid = threadIdx.x;
    const float* qbase = g_qkv + (size_t)(b * L) * (3 * D) + h * HD;
    for (int i = tid; i < 1024; i += 256) {
        int r = i >> 4, c = (i & 15) << 2;
        float4 qv = *(const float4*)(qbase + (size_t)(mt * 64 + r) * (3 * D) + c);
        Qs[c + 0][r] = qv.x; Qs[c + 1][r] = qv.y; Qs[c + 2][r] = qv.z; Qs[c + 3][r] = qv.w;
        float4 kv = *(const float4*)(qbase + D + (size_t)(nt * 64 + r) * (3 * D) + c);
        Ks[c + 0][r] = kv.x; Ks[c + 1][r] = kv.y; Ks[c + 2][r] = kv.z; Ks[c + 3][r] = kv.w;
    }
    __syncthreads();
    int tx = tid & 15, ty = tid >> 4;
    float acc[4][4] = {};
#pragma unroll 4
    for (int d = 0; d < 64; d++) {
        float qa[4], kb[4];
#pragma unroll
        for (int i = 0; i < 4; i++) qa[i] = Qs[d][ty * 4 + i];
#pragma unroll
        for (int j = 0; j < 4; j++) kb[j] = Ks[d][tx * 4 + j];
#pragma unroll
        for (int i = 0; i < 4; i++)
#pragma unroll
            for (int j = 0; j < 4; j++) acc[i][j] = fmaf(qa[i], kb[j], acc[i][j]);
    }
    const float scale = 0.125f;
    float* sbase = g_scores + ((size_t)bh * L + mt * 64 + ty * 4) * L + nt * 64 + tx * 4;
#pragma unroll
    for (int i = 0; i < 4; i++) {
        float4 o = make_float4(acc[i][0] * scale, acc[i][1] * scale,
                               acc[i][2] * scale, acc[i][3] * scale);
        *(float4*)(sbase + (size_t)i * L) = o;
    }
}

// ---------------- attention: row softmax (in place) --------------------------
__global__ void __launch_bounds__(256) softmax_kernel() {
    float* p = g_scores + (size_t)blockIdx.x * L;
    int tid = threadIdx.x;
    float4 v0 = ((const float4*)p)[tid * 2];
    float4 v1 = ((const float4*)p)[tid * 2 + 1];
    float m = fmaxf(fmaxf(fmaxf(v0.x, v0.y), fmaxf(v0.z, v0.w)),
                    fmaxf(fmaxf(v1.x, v1.y), fmaxf(v1.z, v1.w)));
#pragma unroll
    for (int o = 16; o; o >>= 1) m = fmaxf(m, __shfl_xor_sync(0xffffffffu, m, o));
    __shared__ float sred[8];
    __shared__ float s_bcast;
    int w = tid >> 5;
    if ((tid & 31) == 0) sred[w] = m;
    __syncthreads();
    if (tid == 0) {
        float mm = sred[0];
        for (int i = 1; i < 8; i++) mm = fmaxf(mm, sred[i]);
        s_bcast = mm;
    }
    __syncthreads();
    m = s_bcast;
    v0.x = expf(v0.x - m); v0.y = expf(v0.y - m); v0.z = expf(v0.z - m); v0.w = expf(v0.w - m);
    v1.x = expf(v1.x - m); v1.y = expf(v1.y - m); v1.z = expf(v1.z - m); v1.w = expf(v1.w - m);
    float s = v0.x + v0.y + v0.z + v0.w + v1.x + v1.y + v1.z + v1.w;
#pragma unroll
    for (int o = 16; o; o >>= 1) s += __shfl_xor_sync(0xffffffffu, s, o);
    __syncthreads();
    if ((tid & 31) == 0) sred[w] = s;
    __syncthreads();
    if (tid == 0) {
        float t = 0.f;
        for (int i = 0; i < 8; i++) t += sred[i];
        s_bcast = t;
    }
    __syncthreads();
    float inv = 1.0f / s_bcast;
    v0.x *= inv; v0.y *= inv; v0.z *= inv; v0.w *= inv;
    v1.x *= inv; v1.y *= inv; v1.z *= inv; v1.w *= inv;
    ((float4*)p)[tid * 2]     = v0;
    ((float4*)p)[tid * 2 + 1] = v1;
}

// ---------------- attention: out = P @ V -------------------------------------
__global__ void __launch_bounds__(256) attn_pv_kernel() {
    __shared__ float Ps[64][65];
    __shared__ float Vs[64][64];
    int bh = blockIdx.y;
    int b = bh >> 4, h = bh & 15;
    int mt = blockIdx.x;
    int tid = threadIdx.x;
    int tx = tid & 15, ty = tid >> 4;
    const float* vbase = g_qkv + (size_t)(b * L) * (3 * D) + 2 * D + h * HD;
    const float* pbase = g_scores + ((size_t)bh * L + mt * 64) * L;
    float acc[4][4] = {};
    for (int kt = 0; kt < L / 64; kt++) {
        for (int i = tid; i < 1024; i += 256) {
            int r = i >> 4, c = (i & 15) << 2;
            float4 pv = *(const float4*)(pbase + (size_t)r * L + kt * 64 + c);
            Ps[r][c + 0] = pv.x; Ps[r][c + 1] = pv.y; Ps[r][c + 2] = pv.z; Ps[r][c + 3] = pv.w;
            float4 vv = *(const float4*)(vbase + (size_t)(kt * 64 + r) * (3 * D) + c);
            *(float4*)&Vs[r][c] = vv;
        }
        __syncthreads();
#pragma unroll 4
        for (int k = 0; k < 64; k++) {
            float pa[4], vb[4];
#pragma unroll
            for (int i = 0; i < 4; i++) pa[i] = Ps[ty * 4 + i][k];
#pragma unroll
            for (int j = 0; j < 4; j++) vb[j] = Vs[k][tx * 4 + j];
#pragma unroll
            for (int i = 0; i < 4; i++)
#pragma unroll
                for (int j = 0; j < 4; j++) acc[i][j] = fmaf(pa[i], vb[j], acc[i][j]);
        }
        __syncthreads();
    }
    float* obase = g_attno + (size_t)(b * L + mt * 64 + ty * 4) * D + h * HD + tx * 4;
#pragma unroll
    for (int i = 0; i < 4; i++) {
        float4 o = make_float4(acc[i][0], acc[i][1], acc[i][2], acc[i][3]);
        *(float4*)(obase + (size_t)i * D) = o;
    }
}

// ---------------- launch ------------------------------------------------------
extern "C" void kernel_launch(void* const* d_in, const int* in_sizes, int n_in,
                              void* d_out, int out_size) {
    const float* x     = (const float*)d_in[0];
    const float* te    = (const float*)d_in[1];
    const float* Wqkv  = (const float*)d_in[2];
    const float* bqkv  = (const float*)d_in[3];
    const float* Wproj = (const float*)d_in[4];
    const float* bproj = (const float*)d_in[5];
    const float* W1    = (const float*)d_in[6];
    const float* b1    = (const float*)d_in[7];
    const float* W2    = (const float*)d_in[8];
    const float* b2    = (const float*)d_in[9];
    const float* Wt    = (const float*)d_in[10];
    const float* bt    = (const float*)d_in[11];
    const float* g1    = (const float*)d_in[12];
    const float* be1   = (const float*)d_in[13];
    const float* g2    = (const float*)d_in[14];
    const float* be2   = (const float*)d_in[15];
    float* out = (float*)d_out;

    float *p_h, *p_qkv, *p_attno, *p_x1, *p_mlp;
    cudaGetSymbolAddress((void**)&p_h, g_h);
    cudaGetSymbolAddress((void**)&p_qkv, g_qkv);
    cudaGetSymbolAddress((void**)&p_attno, g_attno);
    cudaGetSymbolAddress((void**)&p_x1, g_x1);
    cudaGetSymbolAddress((void**)&p_mlp, g_mlp);

    // 1. time modulation params
    time_proj_kernel<<<dim3(6 * D / 256, NB), 256>>>(te, Wt, bt);
    // 2. LN1 + msa modulation
    ln_mod_kernel<<<ROWS, 256>>>(x, g1, be1, p_h, 0, D);
    // 3. QKV projection (HMMA bf16 split)
    hmma_gemm<0><<<dim3(3 * D / 128, ROWS / 128), 256>>>(
        p_h, Wqkv, bqkv, nullptr, 0, p_qkv, 3 * D, D);
    // 4. attention
    attn_qk_kernel<<<dim3(L / 64, L / 64, NB * H), 256>>>();
    softmax_kernel<<<NB * H * L, 256>>>();
    attn_pv_kernel<<<dim3(L / 64, NB * H), 256>>>();
    // 5. output projection + gated residual -> x1
    hmma_gemm<2><<<dim3(D / 128, ROWS / 128), 256>>>(
        p_attno, Wproj, bproj, x, 2 * D, p_x1, D, D);
    // 6. LN2 + mlp modulation
    ln_mod_kernel<<<ROWS, 256>>>(p_x1, g2, be2, p_h, 3 * D, 4 * D);
    // 7. MLP up + exact GELU
    hmma_gemm<1><<<dim3(MLP / 128, ROWS / 128), 256>>>(
        p_h, W1, b1, nullptr, 0, p_mlp, MLP, D);
    // 8. MLP down + gated residual -> output
    hmma_gemm<2><<<dim3(D / 128, ROWS / 128), 256>>>(
        p_mlp, W2, b2, p_x1, 5 * D, out, D, MLP);
}

// round 4
// speedup vs baseline: 1.9241x; 1.4705x over previous
#include <cuda_runtime.h>
#include <cuda_bf16.h>
#include <math.h>
#include <stdint.h>

// Problem constants
constexpr int D    = 1024;
constexpr int NB   = 4;
constexpr int L    = 2048;
constexpr int H    = 16;
constexpr int HD   = 64;
constexpr int MLP  = 4096;
constexpr int ROWS = NB * L;  // 8192

// ---------------- scratch (device globals; no allocation allowed) ----------
__device__ float g_tp[NB * 6 * D];
__device__ float g_h[(size_t)ROWS * D];
__device__ float g_qkv[(size_t)ROWS * 3 * D];
__device__ float g_attno[(size_t)ROWS * D];
__device__ float g_x1[(size_t)ROWS * D];
__device__ float g_mlp[(size_t)ROWS * MLP];

// =================== helpers ==========================
__device__ __forceinline__ uint32_t smem_u32(const void* p) {
    uint32_t a;
    asm("{ .reg .u64 t; cvta.to.shared.u64 t, %1; cvt.u32.u64 %0, t; }"
        : "=r"(a) : "l"(p));
    return a;
}

// bf16 hi/lo split: (x,y) -> packed hi bf16x2, packed lo bf16x2
__device__ __forceinline__ void split2(float x, float y, uint32_t& hi, uint32_t& lo) {
    __nv_bfloat162 h = __floats2bfloat162_rn(x, y);
    float rx = __bfloat162float(h.x), ry = __bfloat162float(h.y);
    __nv_bfloat162 l = __floats2bfloat162_rn(x - rx, y - ry);
    hi = *reinterpret_cast<uint32_t*>(&h);
    lo = *reinterpret_cast<uint32_t*>(&l);
}

#define LDSM_X4(r0, r1, r2, r3, addr)                                          \
    asm volatile("ldmatrix.sync.aligned.m8n8.x4.shared.b16 {%0,%1,%2,%3}, [%4];" \
                 : "=r"(r0), "=r"(r1), "=r"(r2), "=r"(r3) : "r"(addr))
#define LDSM_X2(r0, r1, addr)                                                  \
    asm volatile("ldmatrix.sync.aligned.m8n8.x2.shared.b16 {%0,%1}, [%2];"     \
                 : "=r"(r0), "=r"(r1) : "r"(addr))
#define MMA_BF16(c, a, b)                                                      \
    asm volatile("mma.sync.aligned.m16n8k16.row.col.f32.bf16.bf16.f32 "        \
                 "{%0,%1,%2,%3}, {%4,%5,%6,%7}, {%8,%9}, {%0,%1,%2,%3};"       \
                 : "+f"((c)[0]), "+f"((c)[1]), "+f"((c)[2]), "+f"((c)[3])      \
                 : "r"((a)[0]), "r"((a)[1]), "r"((a)[2]), "r"((a)[3]),         \
                   "r"((b)[0]), "r"((b)[1]))
#define MMA_BF16_AB(c, a0_, a1_, b0_, b1_)                                     \
    asm volatile("mma.sync.aligned.m16n8k16.row.col.f32.bf16.bf16.f32 "        \
                 "{%0,%1,%2,%3}, {%4,%5,%6,%7}, {%8,%9}, {%0,%1,%2,%3};"       \
                 : "+f"((c)[0]), "+f"((c)[1]), "+f"((c)[2]), "+f"((c)[3])      \
                 : "r"(a0_), "r"(a1_), "r"(a2_), "r"(a3_), "r"(b0_), "r"(b1_))

// ================== HMMA GEMM: C = epi(A @ W + bias) ======================
template <int EPI>
__global__ void __launch_bounds__(256, 1) hmma_gemm(
    const float* __restrict__ A, const float* __restrict__ W,
    const float* __restrict__ bias, const float* __restrict__ res,
    int gate_off, float* __restrict__ C, int N, int K) {
    __shared__ __align__(16) __nv_bfloat16 As_hi[128][40];
    __shared__ __align__(16) __nv_bfloat16 As_lo[128][40];
    __shared__ __align__(16) __nv_bfloat16 Bs_hi[128][40];
    __shared__ __align__(16) __nv_bfloat16 Bs_lo[128][40];

    const int tid  = threadIdx.x;
    const int lane = tid & 31;
    const int warp = tid >> 5;
    const int wm   = warp >> 1;
    const int wn   = warp & 1;
    const int m_base = blockIdx.y * 128;
    const int n_base = blockIdx.x * 128;

    float acc[2][8][4];
#pragma unroll
    for (int mi = 0; mi < 2; mi++)
#pragma unroll
        for (int ni = 0; ni < 8; ni++)
#pragma unroll
            for (int c = 0; c < 4; c++) acc[mi][ni][c] = 0.0f;

    const int a_row = lane & 15;
    const int a_kc  = (lane >> 4) * 8;
    const int b_row = lane & 7;
    const int b_kc  = ((lane >> 3) & 1) * 8;

    const int nblk = K >> 5;
    for (int blk = 0; blk < nblk; blk++) {
        const int k0 = blk << 5;
        float4 av[4];
        int ar4[4], ac4[4];
#pragma unroll
        for (int i = 0; i < 4; i++) {
            int idx = tid + 256 * i;
            ar4[i] = idx >> 3;
            ac4[i] = idx & 7;
            av[i] = *(const float4*)(A + (size_t)(m_base + ar4[i]) * K + k0 + ac4[i] * 4);
        }
        const int nb = tid & 31;
        const int kb = tid >> 5;
        const float* Wp = W + (size_t)(k0 + kb * 4) * N + n_base + nb * 4;
        float4 w0 = *(const float4*)(Wp);
        float4 w1 = *(const float4*)(Wp + (size_t)N);
        float4 w2 = *(const float4*)(Wp + 2 * (size_t)N);
        float4 w3 = *(const float4*)(Wp + 3 * (size_t)N);

        __syncthreads();
#pragma unroll
        for (int i = 0; i < 4; i++) {
            uint32_t h0, l0, h1, l1;
            split2(av[i].x, av[i].y, h0, l0);
            split2(av[i].z, av[i].w, h1, l1);
            *(uint2*)&As_hi[ar4[i]][ac4[i] * 4] = make_uint2(h0, h1);
            *(uint2*)&As_lo[ar4[i]][ac4[i] * 4] = make_uint2(l0, l1);
        }
        {
            float t[4][4] = {{w0.x, w1.x, w2.x, w3.x}, {w0.y, w1.y, w2.y, w3.y},
                             {w0.z, w1.z, w2.z, w3.z}, {w0.w, w1.w, w2.w, w3.w}};
#pragma unroll
            for (int i = 0; i < 4; i++) {
                uint32_t h0, l0, h1, l1;
                split2(t[i][0], t[i][1], h0, l0);
                split2(t[i][2], t[i][3], h1, l1);
                *(uint2*)&Bs_hi[nb * 4 + i][kb * 4] = make_uint2(h0, h1);
                *(uint2*)&Bs_lo[nb * 4 + i][kb * 4] = make_uint2(l0, l1);
            }
        }
        __syncthreads();
#pragma unroll
        for (int ks = 0; ks < 2; ks++) {
            const int kc = ks * 16;
            uint32_t a_h[2][4], a_l[2][4];
#pragma unroll
            for (int mi = 0; mi < 2; mi++) {
                int r = wm * 32 + mi * 16 + a_row;
                LDSM_X4(a_h[mi][0], a_h[mi][1], a_h[mi][2], a_h[mi][3],
                        smem_u32(&As_hi[r][kc + a_kc]));
                LDSM_X4(a_l[mi][0], a_l[mi][1], a_l[mi][2], a_l[mi][3],
                        smem_u32(&As_lo[r][kc + a_kc]));
            }
#pragma unroll
            for (int ni = 0; ni < 8; ni++) {
                int nr = wn * 64 + ni * 8 + b_row;
                uint32_t b_h[2], b_l[2];
                LDSM_X2(b_h[0], b_h[1], smem_u32(&Bs_hi[nr][kc + b_kc]));
                LDSM_X2(b_l[0], b_l[1], smem_u32(&Bs_lo[nr][kc + b_kc]));
#pragma unroll
                for (int mi = 0; mi < 2; mi++) {
                    MMA_BF16(acc[mi][ni], a_h[mi], b_h);
                    MMA_BF16(acc[mi][ni], a_h[mi], b_l);
                    MMA_BF16(acc[mi][ni], a_l[mi], b_h);
                }
            }
        }
    }

    const int col_base = n_base + wn * 64 + (lane & 3) * 2;
    const int row_base = m_base + wm * 32 + (lane >> 2);
#pragma unroll
    for (int mi = 0; mi < 2; mi++) {
#pragma unroll
        for (int half = 0; half < 2; half++) {
            const int m = row_base + mi * 16 + half * 8;
            const int bb = m / L;
#pragma unroll
            for (int ni = 0; ni < 8; ni++) {
                const int col = col_base + ni * 8;
                float2 bv = *(const float2*)(bias + col);
                float vx = acc[mi][ni][half * 2 + 0] + bv.x;
                float vy = acc[mi][ni][half * 2 + 1] + bv.y;
                if (EPI == 1) {
                    vx = 0.5f * vx * (1.0f + erff(vx * 0.7071067811865475f));
                    vy = 0.5f * vy * (1.0f + erff(vy * 0.7071067811865475f));
                }
                if (EPI == 2) {
                    float2 gv = *(const float2*)(g_tp + bb * 6 * D + gate_off + col);
                    float2 rv = *(const float2*)(res + (size_t)m * N + col);
                    vx = rv.x + gv.x * vx;
                    vy = rv.y + gv.y * vy;
                }
                *(float2*)(C + (size_t)m * N + col) = make_float2(vx, vy);
            }
        }
    }
}

// ================== fused flash attention (HMMA bf16 split) ================
// grid (L/128, NB*H), 256 threads. Each warp: 16 q-rows. Online softmax.
// smem layout (bf16 elements):
//   QH/QL: [128][72], KH/KL: [128][72], VH/VL (transposed): [64][136]
constexpr int QK_STRIDE = 72;
constexpr int V_STRIDE  = 136;
constexpr int OFF_QH = 0;
constexpr int OFF_QL = OFF_QH + 128 * QK_STRIDE;
constexpr int OFF_KH = OFF_QL + 128 * QK_STRIDE;
constexpr int OFF_KL = OFF_KH + 128 * QK_STRIDE;
constexpr int OFF_VH = OFF_KL + 128 * QK_STRIDE;
constexpr int OFF_VL = OFF_VH + 64 * V_STRIDE;
constexpr int FA_SMEM = (OFF_VL + 64 * V_STRIDE) * 2;  // bytes

__global__ void __launch_bounds__(256, 1) flash_attn_kernel() {
    extern __shared__ __nv_bfloat16 fs[];
    __nv_bfloat16* qh = fs + OFF_QH;
    __nv_bfloat16* ql = fs + OFF_QL;
    __nv_bfloat16* kh = fs + OFF_KH;
    __nv_bfloat16* kl = fs + OFF_KL;
    __nv_bfloat16* vh = fs + OFF_VH;
    __nv_bfloat16* vl = fs + OFF_VL;

    const int tid  = threadIdx.x;
    const int lane = tid & 31;
    const int wq   = tid >> 5;          // warp id: q-row group
    const int qt   = blockIdx.x;        // q tile
    const int b    = blockIdx.y >> 4;
    const int h    = blockIdx.y & 15;

    const float* qbase = g_qkv + (size_t)(b * L + qt * 128) * (3 * D) + h * HD;

    // ---- stage Q (scaled by 2^-3, split hi/lo) ----
#pragma unroll
    for (int i = 0; i < 8; i++) {
        int idx = tid + 256 * i;
        int row = idx >> 4, c4 = (idx & 15) * 4;
        float4 v = *(const float4*)(qbase + (size_t)row * (3 * D) + c4);
        v.x *= 0.125f; v.y *= 0.125f; v.z *= 0.125f; v.w *= 0.125f;
        uint32_t h0, l0, h1, l1;
        split2(v.x, v.y, h0, l0);
        split2(v.z, v.w, h1, l1);
        *(uint2*)&qh[row * QK_STRIDE + c4] = make_uint2(h0, h1);
        *(uint2*)&ql[row * QK_STRIDE + c4] = make_uint2(l0, l1);
    }
    __syncthreads();

    // ---- load Q fragments (persist across K loop) ----
    const int a_row = lane & 15;
    const int a_kc  = (lane >> 4) * 8;
    uint32_t qa_h[4][4], qa_l[4][4];
#pragma unroll
    for (int ks = 0; ks < 4; ks++) {
        LDSM_X4(qa_h[ks][0], qa_h[ks][1], qa_h[ks][2], qa_h[ks][3],
                smem_u32(&qh[(wq * 16 + a_row) * QK_STRIDE + ks * 16 + a_kc]));
        LDSM_X4(qa_l[ks][0], qa_l[ks][1], qa_l[ks][2], qa_l[ks][3],
                smem_u32(&ql[(wq * 16 + a_row) * QK_STRIDE + ks * 16 + a_kc]));
    }

    // b-frag ldmatrix addressing (16 rows x 16 cols -> two n8 frags)
    const int kb_row = (lane >> 4) * 8 + (lane & 7);
    const int kb_kc  = ((lane >> 3) & 1) * 8;

    float oacc[8][4];
#pragma unroll
    for (int nj = 0; nj < 8; nj++)
#pragma unroll
        for (int c = 0; c < 4; c++) oacc[nj][c] = 0.0f;
    float m0 = -INFINITY, m1 = -INFINITY, l0 = 0.0f, l1 = 0.0f;

    const float* kvbase = g_qkv + (size_t)(b * L) * (3 * D) + h * HD;

    for (int kt = 0; kt < L / 128; kt++) {
        // ---- stage K tile [128][64] hi/lo ----
        const float* kptr = kvbase + (size_t)(kt * 128) * (3 * D) + D;
        const float* vptr = kvbase + (size_t)(kt * 128) * (3 * D) + 2 * D;
        __syncthreads();  // previous iter's compute done with K/V smem
#pragma unroll
        for (int i = 0; i < 8; i++) {
            int idx = tid + 256 * i;
            int row = idx >> 4, c4 = (idx & 15) * 4;
            float4 v = *(const float4*)(kptr + (size_t)row * (3 * D) + c4);
            uint32_t h0, l0_, h1, l1_;
            split2(v.x, v.y, h0, l0_);
            split2(v.z, v.w, h1, l1_);
            *(uint2*)&kh[row * QK_STRIDE + c4] = make_uint2(h0, h1);
            *(uint2*)&kl[row * QK_STRIDE + c4] = make_uint2(l0_, l1_);
        }
        // ---- stage V transposed [64 hd][128 tok] hi/lo ----
        {
            const int hd_g = tid & 15;
            const int tg0  = tid >> 4;
#pragma unroll
            for (int p = 0; p < 2; p++) {
                int tok_g = tg0 + p * 16;
                const float* vp = vptr + (size_t)(tok_g * 4) * (3 * D) + hd_g * 4;
                float4 w0 = *(const float4*)(vp);
                float4 w1 = *(const float4*)(vp + (size_t)(3 * D));
                float4 w2 = *(const float4*)(vp + 2 * (size_t)(3 * D));
                float4 w3 = *(const float4*)(vp + 3 * (size_t)(3 * D));
                float t[4][4] = {{w0.x, w1.x, w2.x, w3.x}, {w0.y, w1.y, w2.y, w3.y},
                                 {w0.z, w1.z, w2.z, w3.z}, {w0.w, w1.w, w2.w, w3.w}};
#pragma unroll
                for (int i = 0; i < 4; i++) {
                    uint32_t h0, l0_, h1, l1_;
                    split2(t[i][0], t[i][1], h0, l0_);
                    split2(t[i][2], t[i][3], h1, l1_);
                    *(uint2*)&vh[(hd_g * 4 + i) * V_STRIDE + tok_g * 4] = make_uint2(h0, h1);
                    *(uint2*)&vl[(hd_g * 4 + i) * V_STRIDE + tok_g * 4] = make_uint2(l0_, l1_);
                }
            }
        }
        __syncthreads();

        // ---- S = Q K^T (3-term split), scaled already ----
        float sacc[16][4];
#pragma unroll
        for (int ni = 0; ni < 16; ni++)
#pragma unroll
            for (int c = 0; c < 4; c++) sacc[ni][c] = 0.0f;
#pragma unroll
        for (int ks = 0; ks < 4; ks++) {
#pragma unroll
            for (int nip = 0; nip < 8; nip++) {
                uint32_t bh[4], bl[4];
                LDSM_X4(bh[0], bh[1], bh[2], bh[3],
                        smem_u32(&kh[(nip * 16 + kb_row) * QK_STRIDE + ks * 16 + kb_kc]));
                LDSM_X4(bl[0], bl[1], bl[2], bl[3],
                        smem_u32(&kl[(nip * 16 + kb_row) * QK_STRIDE + ks * 16 + kb_kc]));
                MMA_BF16(sacc[2 * nip],     qa_h[ks], (bh));
                MMA_BF16(sacc[2 * nip],     qa_h[ks], (bl));
                MMA_BF16(sacc[2 * nip],     qa_l[ks], (bh));
                MMA_BF16(sacc[2 * nip + 1], qa_h[ks], (bh + 2));
                MMA_BF16(sacc[2 * nip + 1], qa_h[ks], (bl + 2));
                MMA_BF16(sacc[2 * nip + 1], qa_l[ks], (bh + 2));
            }
        }

        // ---- online softmax ----
        float t0 = -INFINITY, t1 = -INFINITY;
#pragma unroll
        for (int ni = 0; ni < 16; ni++) {
            t0 = fmaxf(t0, fmaxf(sacc[ni][0], sacc[ni][1]));
            t1 = fmaxf(t1, fmaxf(sacc[ni][2], sacc[ni][3]));
        }
        t0 = fmaxf(t0, __shfl_xor_sync(0xffffffffu, t0, 1));
        t0 = fmaxf(t0, __shfl_xor_sync(0xffffffffu, t0, 2));
        t1 = fmaxf(t1, __shfl_xor_sync(0xffffffffu, t1, 1));
        t1 = fmaxf(t1, __shfl_xor_sync(0xffffffffu, t1, 2));
        float nm0 = fmaxf(m0, t0), nm1 = fmaxf(m1, t1);
        float al0 = __expf(m0 - nm0), al1 = __expf(m1 - nm1);
        float rs0 = 0.0f, rs1 = 0.0f;
#pragma unroll
        for (int ni = 0; ni < 16; ni++) {
            sacc[ni][0] = __expf(sacc[ni][0] - nm0);
            sacc[ni][1] = __expf(sacc[ni][1] - nm0);
            sacc[ni][2] = __expf(sacc[ni][2] - nm1);
            sacc[ni][3] = __expf(sacc[ni][3] - nm1);
            rs0 += sacc[ni][0] + sacc[ni][1];
            rs1 += sacc[ni][2] + sacc[ni][3];
        }
        rs0 += __shfl_xor_sync(0xffffffffu, rs0, 1);
        rs0 += __shfl_xor_sync(0xffffffffu, rs0, 2);
        rs1 += __shfl_xor_sync(0xffffffffu, rs1, 1);
        rs1 += __shfl_xor_sync(0xffffffffu, rs1, 2);
        l0 = l0 * al0 + rs0;
        l1 = l1 * al1 + rs1;
        m0 = nm0; m1 = nm1;
#pragma unroll
        for (int nj = 0; nj < 8; nj++) {
            oacc[nj][0] *= al0; oacc[nj][1] *= al0;
            oacc[nj][2] *= al1; oacc[nj][3] *= al1;
        }

        // ---- O += P V (P split in regs, V split in smem) ----
#pragma unroll
        for (int kp = 0; kp < 8; kp++) {
            uint32_t pa_h[4], pa_l[4];
            split2(sacc[2 * kp][0],     sacc[2 * kp][1],     pa_h[0], pa_l[0]);
            split2(sacc[2 * kp][2],     sacc[2 * kp][3],     pa_h[1], pa_l[1]);
            split2(sacc[2 * kp + 1][0], sacc[2 * kp + 1][1], pa_h[2], pa_l[2]);
            split2(sacc[2 * kp + 1][2], sacc[2 * kp + 1][3], pa_h[3], pa_l[3]);
#pragma unroll
            for (int njp = 0; njp < 4; njp++) {
                uint32_t vbh[4], vbl[4];
                LDSM_X4(vbh[0], vbh[1], vbh[2], vbh[3],
                        smem_u32(&vh[(njp * 16 + kb_row) * V_STRIDE + kp * 16 + kb_kc]));
                LDSM_X4(vbl[0], vbl[1], vbl[2], vbl[3],
                        smem_u32(&vl[(njp * 16 + kb_row) * V_STRIDE + kp * 16 + kb_kc]));
                MMA_BF16(oacc[2 * njp],     pa_h, (vbh));
                MMA_BF16(oacc[2 * njp],     pa_h, (vbl));
                MMA_BF16(oacc[2 * njp],     pa_l, (vbh));
                MMA_BF16(oacc[2 * njp + 1], pa_h, (vbh + 2));
                MMA_BF16(oacc[2 * njp + 1], pa_h, (vbl + 2));
                MMA_BF16(oacc[2 * njp + 1], pa_l, (vbh + 2));
            }
        }
    }

    // ---- epilogue: normalize + write ----
    float inv0 = 1.0f / l0, inv1 = 1.0f / l1;
    const int row0 = qt * 128 + wq * 16 + (lane >> 2);
    float* ob = g_attno + (size_t)(b * L + row0) * D + h * HD + (lane & 3) * 2;
#pragma unroll
    for (int nj = 0; nj < 8; nj++) {
        *(float2*)(ob + nj * 8) =
            make_float2(oacc[nj][0] * inv0, oacc[nj][1] * inv0);
        *(float2*)(ob + 8 * D + nj * 8) =
            make_float2(oacc[nj][2] * inv1, oacc[nj][3] * inv1);
    }
}

// ---------------- time embedding projection --------------------------------
__global__ void time_proj_kernel(const float* __restrict__ te,
                                 const float* __restrict__ Wt,
                                 const float* __restrict__ bt) {
    __shared__ float s[D];
    int b   = blockIdx.y;
    int tid = threadIdx.x;
    for (int i = tid; i < D; i += 256) {
        float v = te[b * D + i];
        s[i] = v / (1.0f + expf(-v));
    }
    __syncthreads();
    int j = blockIdx.x * 256 + tid;
    float acc = bt[j];
#pragma unroll 8
    for (int k = 0; k < D; k++) acc = fmaf(s[k], Wt[(size_t)k * (6 * D) + j], acc);
    g_tp[b * 6 * D + j] = acc;
}

// ---------------- LayerNorm + AdaLN modulation ------------------------------
__global__ void ln_mod_kernel(const float* __restrict__ x,
                              const float* __restrict__ g,
                              const float* __restrict__ be,
                              float* __restrict__ out,
                              int shift_off, int scale_off) {
    int row = blockIdx.x;
    int b   = row / L;
    const float* xr = x + (size_t)row * D;
    int tid = threadIdx.x;
    float4 v = ((const float4*)xr)[tid];
    float s = v.x + v.y + v.z + v.w;
    float q = v.x * v.x + v.y * v.y + v.z * v.z + v.w * v.w;
#pragma unroll
    for (int o = 16; o; o >>= 1) {
        s += __shfl_xor_sync(0xffffffffu, s, o);
        q += __shfl_xor_sync(0xffffffffu, q, o);
    }
    __shared__ float ss[8], sq[8];
    __shared__ float s_mu, s_rs;
    int w = tid >> 5;
    if ((tid & 31) == 0) { ss[w] = s; sq[w] = q; }
    __syncthreads();
    if (tid == 0) {
        float S = 0.f, Q = 0.f;
        for (int i = 0; i < 8; i++) { S += ss[i]; Q += sq[i]; }
        float mu  = S / D;
        float var = Q / D - mu * mu;
        s_mu = mu;
        s_rs = rsqrtf(var + 1e-5f);
    }
    __syncthreads();
    float mu = s_mu, rs = s_rs;
    int j = tid * 4;
    const float* tpb = g_tp + b * 6 * D;
    float4 gv = ((const float4*)g)[tid];
    float4 bv = ((const float4*)be)[tid];
    float4 sc = *(const float4*)(tpb + scale_off + j);
    float4 sh = *(const float4*)(tpb + shift_off + j);
    float4 o;
    o.x = ((v.x - mu) * rs * gv.x + bv.x) * (1.0f + sc.x) + sh.x;
    o.y = ((v.y - mu) * rs * gv.y + bv.y) * (1.0f + sc.y) + sh.y;
    o.z = ((v.z - mu) * rs * gv.z + bv.z) * (1.0f + sc.z) + sh.z;
    o.w = ((v.w - mu) * rs * gv.w + bv.w) * (1.0f + sc.w) + sh.w;
    ((float4*)(out + (size_t)row * D))[tid] = o;
}

// ---------------- launch ------------------------------------------------------
extern "C" void kernel_launch(void* const* d_in, const int* in_sizes, int n_in,
                              void* d_out, int out_size) {
    const float* x     = (const float*)d_in[0];
    const float* te    = (const float*)d_in[1];
    const float* Wqkv  = (const float*)d_in[2];
    const float* bqkv  = (const float*)d_in[3];
    const float* Wproj = (const float*)d_in[4];
    const float* bproj = (const float*)d_in[5];
    const float* W1    = (const float*)d_in[6];
    const float* b1    = (const float*)d_in[7];
    const float* W2    = (const float*)d_in[8];
    const float* b2    = (const float*)d_in[9];
    const float* Wt    = (const float*)d_in[10];
    const float* bt    = (const float*)d_in[11];
    const float* g1    = (const float*)d_in[12];
    const float* be1   = (const float*)d_in[13];
    const float* g2    = (const float*)d_in[14];
    const float* be2   = (const float*)d_in[15];
    float* out = (float*)d_out;

    float *p_h, *p_qkv, *p_attno, *p_x1, *p_mlp;
    cudaGetSymbolAddress((void**)&p_h, g_h);
    cudaGetSymbolAddress((void**)&p_qkv, g_qkv);
    cudaGetSymbolAddress((void**)&p_attno, g_attno);
    cudaGetSymbolAddress((void**)&p_x1, g_x1);
    cudaGetSymbolAddress((void**)&p_mlp, g_mlp);

    cudaFuncSetAttribute(flash_attn_kernel,
                         cudaFuncAttributeMaxDynamicSharedMemorySize, FA_SMEM);

    // 1. time modulation params
    time_proj_kernel<<<dim3(6 * D / 256, NB), 256>>>(te, Wt, bt);
    // 2. LN1 + msa modulation
    ln_mod_kernel<<<ROWS, 256>>>(x, g1, be1, p_h, 0, D);
    // 3. QKV projection (HMMA bf16 split)
    hmma_gemm<0><<<dim3(3 * D / 128, ROWS / 128), 256>>>(
        p_h, Wqkv, bqkv, nullptr, 0, p_qkv, 3 * D, D);
    // 4. fused flash attention
    flash_attn_kernel<<<dim3(L / 128, NB * H), 256, FA_SMEM>>>();
    // 5. output projection + gated residual -> x1
    hmma_gemm<2><<<dim3(D / 128, ROWS / 128), 256>>>(
        p_attno, Wproj, bproj, x, 2 * D, p_x1, D, D);
    // 6. LN2 + mlp modulation
    ln_mod_kernel<<<ROWS, 256>>>(p_x1, g2, be2, p_h, 3 * D, 4 * D);
    // 7. MLP up + exact GELU
    hmma_gemm<1><<<dim3(MLP / 128, ROWS / 128), 256>>>(
        p_h, W1, b1, nullptr, 0, p_mlp, MLP, D);
    // 8. MLP down + gated residual -> output
    hmma_gemm<2><<<dim3(D / 128, ROWS / 128), 256>>>(
        p_mlp, W2, b2, p_x1, 5 * D, out, D, MLP);
}

// round 5
// speedup vs baseline: 2.9013x; 1.5079x over previous
#include <cuda_runtime.h>
#include <cuda_bf16.h>
#include <math.h>
#include <stdint.h>

// Problem constants
constexpr int D    = 1024;
constexpr int NB   = 4;
constexpr int L    = 2048;
constexpr int H    = 16;
constexpr int HD   = 64;
constexpr int MLP  = 4096;
constexpr int ROWS = NB * L;  // 8192

// ---------------- scratch (device globals; no allocation allowed) ----------
__device__ float g_tp[NB * 6 * D];
__device__ float g_qkv[(size_t)ROWS * 3 * D];
__device__ float g_x1[(size_t)ROWS * D];
// bf16 hi/lo activation buffers
__device__ __nv_bfloat16 g_h_h[(size_t)ROWS * D];
__device__ __nv_bfloat16 g_h_l[(size_t)ROWS * D];
__device__ __nv_bfloat16 g_at_h[(size_t)ROWS * D];
__device__ __nv_bfloat16 g_at_l[(size_t)ROWS * D];
__device__ __nv_bfloat16 g_mlp_h[(size_t)ROWS * MLP];
__device__ __nv_bfloat16 g_mlp_l[(size_t)ROWS * MLP];
// bf16 hi/lo transposed weights [N][K]
__device__ __nv_bfloat16 g_wqkv_h[3 * D * D];
__device__ __nv_bfloat16 g_wqkv_l[3 * D * D];
__device__ __nv_bfloat16 g_wproj_h[D * D];
__device__ __nv_bfloat16 g_wproj_l[D * D];
__device__ __nv_bfloat16 g_w1_h[D * MLP];
__device__ __nv_bfloat16 g_w1_l[D * MLP];
__device__ __nv_bfloat16 g_w2_h[MLP * D];
__device__ __nv_bfloat16 g_w2_l[MLP * D];

// =================== helpers ==========================
__device__ __forceinline__ uint32_t smem_u32(const void* p) {
    uint32_t a;
    asm("{ .reg .u64 t; cvta.to.shared.u64 t, %1; cvt.u32.u64 %0, t; }"
        : "=r"(a) : "l"(p));
    return a;
}
__device__ __forceinline__ void split2(float x, float y, uint32_t& hi, uint32_t& lo) {
    __nv_bfloat162 h = __floats2bfloat162_rn(x, y);
    float rx = __bfloat162float(h.x), ry = __bfloat162float(h.y);
    __nv_bfloat162 l = __floats2bfloat162_rn(x - rx, y - ry);
    hi = *reinterpret_cast<uint32_t*>(&h);
    lo = *reinterpret_cast<uint32_t*>(&l);
}
__device__ __forceinline__ void cp16(uint32_t saddr, const void* g) {
    asm volatile("cp.async.cg.shared.global [%0], [%1], 16;" :: "r"(saddr), "l"(g));
}
#define CP_COMMIT() asm volatile("cp.async.commit_group;" ::: "memory")
#define CP_WAIT(n)  asm volatile("cp.async.wait_group %0;" :: "n"(n) : "memory")

#define LDSM_X4(r0, r1, r2, r3, addr)                                          \
    asm volatile("ldmatrix.sync.aligned.m8n8.x4.shared.b16 {%0,%1,%2,%3}, [%4];" \
                 : "=r"(r0), "=r"(r1), "=r"(r2), "=r"(r3) : "r"(addr))
#define LDSM_X2(r0, r1, addr)                                                  \
    asm volatile("ldmatrix.sync.aligned.m8n8.x2.shared.b16 {%0,%1}, [%2];"     \
                 : "=r"(r0), "=r"(r1) : "r"(addr))
#define MMA_BF16(c, a, b)                                                      \
    asm volatile("mma.sync.aligned.m16n8k16.row.col.f32.bf16.bf16.f32 "        \
                 "{%0,%1,%2,%3}, {%4,%5,%6,%7}, {%8,%9}, {%0,%1,%2,%3};"       \
                 : "+f"((c)[0]), "+f"((c)[1]), "+f"((c)[2]), "+f"((c)[3])      \
                 : "r"((a)[0]), "r"((a)[1]), "r"((a)[2]), "r"((a)[3]),         \
                   "r"((b)[0]), "r"((b)[1]))

// ============ weight convert+transpose: W[K][N] f32 -> Wh/Wl[N][K] bf16 ====
__global__ void wconv_kernel(const float* __restrict__ W,
                             __nv_bfloat16* __restrict__ Wh,
                             __nv_bfloat16* __restrict__ Wl, int K, int N) {
    __shared__ float s[32][33];
    const int tid = threadIdx.x;
    const int tx = tid & 31, ty = tid >> 5;
    const int n0 = blockIdx.x * 32, k0 = blockIdx.y * 32;
#pragma unroll
    for (int p = 0; p < 4; p++)
        s[ty + 8 * p][tx] = W[(size_t)(k0 + ty + 8 * p) * N + n0 + tx];
    __syncthreads();
#pragma unroll
    for (int p = 0; p < 4; p++) {
        float v = s[tx][ty + 8 * p];
        __nv_bfloat16 h = __float2bfloat16(v);
        __nv_bfloat16 l = __float2bfloat16(v - __bfloat162float(h));
        size_t o = (size_t)(n0 + ty + 8 * p) * K + k0 + tx;
        Wh[o] = h;
        Wl[o] = l;
    }
}

// ================== HMMA GEMM v2: bf16 hi/lo in, cp.async pipeline =========
// A(h/l) [M][K] bf16, B(h/l) [N][K] bf16. 128x128 CTA tile, BK=32, 2 stages.
// EPI 0: bias. EPI 1: exact GELU. EPI 2: res + gate*(acc+bias).
// OUTK 0: fp32 C. OUTK 1: bf16 hi/lo Ch/Cl.
constexpr int GT_ROWB  = 80;                    // 40 bf16 per row
constexpr int GT_TILE  = 128 * GT_ROWB;         // 10240 B
constexpr int GT_STAGE = 4 * GT_TILE;           // 40960 B
constexpr int GT_SMEM  = 2 * GT_STAGE;          // 81920 B

template <int EPI, int OUTK>
__global__ void __launch_bounds__(256, 2) hgemm(
    const __nv_bfloat16* __restrict__ Ah, const __nv_bfloat16* __restrict__ Al,
    const __nv_bfloat16* __restrict__ Bh, const __nv_bfloat16* __restrict__ Bl,
    const float* __restrict__ bias, const float* __restrict__ res, int gate_off,
    float* __restrict__ C, __nv_bfloat16* __restrict__ Ch,
    __nv_bfloat16* __restrict__ Cl, int N, int K) {
    extern __shared__ char smem[];
    const uint32_t sbase = smem_u32(smem);
    const int tid  = threadIdx.x;
    const int lane = tid & 31;
    const int warp = tid >> 5;
    const int wm   = warp >> 1;
    const int wn   = warp & 1;
    const int m_base = blockIdx.y * 128;
    const int n_base = blockIdx.x * 128;

    // cp.async mapping: per tile 512 chunks (row = c>>2, 16B col = c&3)
    const int c0r = tid >> 2, c0c = tid & 3;
    const int c1r = (tid + 256) >> 2, c1c = c0c;
    const __nv_bfloat16* srcs[4] = {Ah + (size_t)(m_base + 0) * K,
                                    Al + (size_t)(m_base + 0) * K,
                                    Bh + (size_t)(n_base + 0) * K,
                                    Bl + (size_t)(n_base + 0) * K};

    auto load_stage = [&](int stage, int k0) {
        uint32_t sb = sbase + stage * GT_STAGE;
#pragma unroll
        for (int t = 0; t < 4; t++) {
            const __nv_bfloat16* g = srcs[t] + k0;
            cp16(sb + t * GT_TILE + c0r * GT_ROWB + c0c * 16,
                 g + (size_t)c0r * K + c0c * 8);
            cp16(sb + t * GT_TILE + c1r * GT_ROWB + c1c * 16,
                 g + (size_t)c1r * K + c1c * 8);
        }
    };

    float acc[2][8][4];
#pragma unroll
    for (int mi = 0; mi < 2; mi++)
#pragma unroll
        for (int ni = 0; ni < 8; ni++)
#pragma unroll
            for (int c = 0; c < 4; c++) acc[mi][ni][c] = 0.0f;

    const int a_row = lane & 15;
    const int a_kc  = (lane >> 4) * 8;
    const int b_row = lane & 7;
    const int b_kc  = ((lane >> 3) & 1) * 8;

    const int nblk = K >> 5;
    load_stage(0, 0);
    CP_COMMIT();
    load_stage(1, 32);
    CP_COMMIT();

    for (int blk = 0; blk < nblk; blk++) {
        if (blk == nblk - 1) CP_WAIT(0); else CP_WAIT(1);
        __syncthreads();
        const uint32_t sb = sbase + (blk & 1) * GT_STAGE;
        const uint32_t s_ah = sb;
        const uint32_t s_al = sb + GT_TILE;
        const uint32_t s_bh = sb + 2 * GT_TILE;
        const uint32_t s_bl = sb + 3 * GT_TILE;
#pragma unroll
        for (int ks = 0; ks < 2; ks++) {
            const int kc = ks * 16;
            uint32_t a_h[2][4], a_l[2][4];
#pragma unroll
            for (int mi = 0; mi < 2; mi++) {
                uint32_t ra = (wm * 32 + mi * 16 + a_row) * GT_ROWB + (kc + a_kc) * 2;
                LDSM_X4(a_h[mi][0], a_h[mi][1], a_h[mi][2], a_h[mi][3], s_ah + ra);
                LDSM_X4(a_l[mi][0], a_l[mi][1], a_l[mi][2], a_l[mi][3], s_al + ra);
            }
#pragma unroll
            for (int ni = 0; ni < 8; ni++) {
                uint32_t rb = (wn * 64 + ni * 8 + b_row) * GT_ROWB + (kc + b_kc) * 2;
                uint32_t b_h[2], b_l[2];
                LDSM_X2(b_h[0], b_h[1], s_bh + rb);
                LDSM_X2(b_l[0], b_l[1], s_bl + rb);
#pragma unroll
                for (int mi = 0; mi < 2; mi++) {
                    MMA_BF16(acc[mi][ni], a_h[mi], b_h);
                    MMA_BF16(acc[mi][ni], a_h[mi], b_l);
                    MMA_BF16(acc[mi][ni], a_l[mi], b_h);
                }
            }
        }
        __syncthreads();
        if (blk + 2 < nblk) {
            load_stage(blk & 1, (blk + 2) << 5);
            CP_COMMIT();
        }
    }

    // ---- epilogue ----
    const int col_base = n_base + wn * 64 + (lane & 3) * 2;
    const int row_base = m_base + wm * 32 + (lane >> 2);
#pragma unroll
    for (int mi = 0; mi < 2; mi++) {
#pragma unroll
        for (int half = 0; half < 2; half++) {
            const int m = row_base + mi * 16 + half * 8;
            const int bb = m / L;
#pragma unroll
            for (int ni = 0; ni < 8; ni++) {
                const int col = col_base + ni * 8;
                float2 bv = *(const float2*)(bias + col);
                float vx = acc[mi][ni][half * 2 + 0] + bv.x;
                float vy = acc[mi][ni][half * 2 + 1] + bv.y;
                if (EPI == 1) {
                    vx = 0.5f * vx * (1.0f + erff(vx * 0.7071067811865475f));
                    vy = 0.5f * vy * (1.0f + erff(vy * 0.7071067811865475f));
                }
                if (EPI == 2) {
                    float2 gv = *(const float2*)(g_tp + bb * 6 * D + gate_off + col);
                    float2 rv = *(const float2*)(res + (size_t)m * N + col);
                    vx = rv.x + gv.x * vx;
                    vy = rv.y + gv.y * vy;
                }
                if (OUTK == 0) {
                    *(float2*)(C + (size_t)m * N + col) = make_float2(vx, vy);
                } else {
                    uint32_t hh, ll;
                    split2(vx, vy, hh, ll);
                    *(uint32_t*)&Ch[(size_t)m * N + col] = hh;
                    *(uint32_t*)&Cl[(size_t)m * N + col] = ll;
                }
            }
        }
    }
}

// ================== fused flash attention (HMMA bf16 split) ================
constexpr int QK_STRIDE = 72;
constexpr int V_STRIDE  = 136;
constexpr int OFF_QH = 0;
constexpr int OFF_QL = OFF_QH + 128 * QK_STRIDE;
constexpr int OFF_KH = OFF_QL + 128 * QK_STRIDE;
constexpr int OFF_KL = OFF_KH + 128 * QK_STRIDE;
constexpr int OFF_VH = OFF_KL + 128 * QK_STRIDE;
constexpr int OFF_VL = OFF_VH + 64 * V_STRIDE;
constexpr int FA_SMEM = (OFF_VL + 64 * V_STRIDE) * 2;

__global__ void __launch_bounds__(256, 1) flash_attn_kernel() {
    extern __shared__ __nv_bfloat16 fs[];
    __nv_bfloat16* qh = fs + OFF_QH;
    __nv_bfloat16* ql = fs + OFF_QL;
    __nv_bfloat16* kh = fs + OFF_KH;
    __nv_bfloat16* kl = fs + OFF_KL;
    __nv_bfloat16* vh = fs + OFF_VH;
    __nv_bfloat16* vl = fs + OFF_VL;

    const int tid  = threadIdx.x;
    const int lane = tid & 31;
    const int wq   = tid >> 5;
    const int qt   = blockIdx.x;
    const int b    = blockIdx.y >> 4;
    const int h    = blockIdx.y & 15;

    const float* qbase = g_qkv + (size_t)(b * L + qt * 128) * (3 * D) + h * HD;

#pragma unroll
    for (int i = 0; i < 8; i++) {
        int idx = tid + 256 * i;
        int row = idx >> 4, c4 = (idx & 15) * 4;
        float4 v = *(const float4*)(qbase + (size_t)row * (3 * D) + c4);
        v.x *= 0.125f; v.y *= 0.125f; v.z *= 0.125f; v.w *= 0.125f;
        uint32_t h0, l0, h1, l1;
        split2(v.x, v.y, h0, l0);
        split2(v.z, v.w, h1, l1);
        *(uint2*)&qh[row * QK_STRIDE + c4] = make_uint2(h0, h1);
        *(uint2*)&ql[row * QK_STRIDE + c4] = make_uint2(l0, l1);
    }
    __syncthreads();

    const int a_row = lane & 15;
    const int a_kc  = (lane >> 4) * 8;
    uint32_t qa_h[4][4], qa_l[4][4];
#pragma unroll
    for (int ks = 0; ks < 4; ks++) {
        LDSM_X4(qa_h[ks][0], qa_h[ks][1], qa_h[ks][2], qa_h[ks][3],
                smem_u32(&qh[(wq * 16 + a_row) * QK_STRIDE + ks * 16 + a_kc]));
        LDSM_X4(qa_l[ks][0], qa_l[ks][1], qa_l[ks][2], qa_l[ks][3],
                smem_u32(&ql[(wq * 16 + a_row) * QK_STRIDE + ks * 16 + a_kc]));
    }

    const int kb_row = (lane >> 4) * 8 + (lane & 7);
    const int kb_kc  = ((lane >> 3) & 1) * 8;

    float oacc[8][4];
#pragma unroll
    for (int nj = 0; nj < 8; nj++)
#pragma unroll
        for (int c = 0; c < 4; c++) oacc[nj][c] = 0.0f;
    float m0 = -INFINITY, m1 = -INFINITY, l0 = 0.0f, l1 = 0.0f;

    const float* kvbase = g_qkv + (size_t)(b * L) * (3 * D) + h * HD;

    for (int kt = 0; kt < L / 128; kt++) {
        const float* kptr = kvbase + (size_t)(kt * 128) * (3 * D) + D;
        const float* vptr = kvbase + (size_t)(kt * 128) * (3 * D) + 2 * D;
        __syncthreads();
#pragma unroll
        for (int i = 0; i < 8; i++) {
            int idx = tid + 256 * i;
            int row = idx >> 4, c4 = (idx & 15) * 4;
            float4 v = *(const float4*)(kptr + (size_t)row * (3 * D) + c4);
            uint32_t h0, l0_, h1, l1_;
            split2(v.x, v.y, h0, l0_);
            split2(v.z, v.w, h1, l1_);
            *(uint2*)&kh[row * QK_STRIDE + c4] = make_uint2(h0, h1);
            *(uint2*)&kl[row * QK_STRIDE + c4] = make_uint2(l0_, l1_);
        }
        {
            const int hd_g = tid & 15;
            const int tg0  = tid >> 4;
#pragma unroll
            for (int p = 0; p < 2; p++) {
                int tok_g = tg0 + p * 16;
                const float* vp = vptr + (size_t)(tok_g * 4) * (3 * D) + hd_g * 4;
                float4 w0 = *(const float4*)(vp);
                float4 w1 = *(const float4*)(vp + (size_t)(3 * D));
                float4 w2 = *(const float4*)(vp + 2 * (size_t)(3 * D));
                float4 w3 = *(const float4*)(vp + 3 * (size_t)(3 * D));
                float t[4][4] = {{w0.x, w1.x, w2.x, w3.x}, {w0.y, w1.y, w2.y, w3.y},
                                 {w0.z, w1.z, w2.z, w3.z}, {w0.w, w1.w, w2.w, w3.w}};
#pragma unroll
                for (int i = 0; i < 4; i++) {
                    uint32_t h0, l0_, h1, l1_;
                    split2(t[i][0], t[i][1], h0, l0_);
                    split2(t[i][2], t[i][3], h1, l1_);
                    *(uint2*)&vh[(hd_g * 4 + i) * V_STRIDE + tok_g * 4] = make_uint2(h0, h1);
                    *(uint2*)&vl[(hd_g * 4 + i) * V_STRIDE + tok_g * 4] = make_uint2(l0_, l1_);
                }
            }
        }
        __syncthreads();

        float sacc[16][4];
#pragma unroll
        for (int ni = 0; ni < 16; ni++)
#pragma unroll
            for (int c = 0; c < 4; c++) sacc[ni][c] = 0.0f;
#pragma unroll
        for (int ks = 0; ks < 4; ks++) {
#pragma unroll
            for (int nip = 0; nip < 8; nip++) {
                uint32_t bh[4], bl[4];
                LDSM_X4(bh[0], bh[1], bh[2], bh[3],
                        smem_u32(&kh[(nip * 16 + kb_row) * QK_STRIDE + ks * 16 + kb_kc]));
                LDSM_X4(bl[0], bl[1], bl[2], bl[3],
                        smem_u32(&kl[(nip * 16 + kb_row) * QK_STRIDE + ks * 16 + kb_kc]));
                MMA_BF16(sacc[2 * nip],     qa_h[ks], (bh));
                MMA_BF16(sacc[2 * nip],     qa_h[ks], (bl));
                MMA_BF16(sacc[2 * nip],     qa_l[ks], (bh));
                MMA_BF16(sacc[2 * nip + 1], qa_h[ks], (bh + 2));
                MMA_BF16(sacc[2 * nip + 1], qa_h[ks], (bl + 2));
                MMA_BF16(sacc[2 * nip + 1], qa_l[ks], (bh + 2));
            }
        }

        float t0 = -INFINITY, t1 = -INFINITY;
#pragma unroll
        for (int ni = 0; ni < 16; ni++) {
            t0 = fmaxf(t0, fmaxf(sacc[ni][0], sacc[ni][1]));
            t1 = fmaxf(t1, fmaxf(sacc[ni][2], sacc[ni][3]));
        }
        t0 = fmaxf(t0, __shfl_xor_sync(0xffffffffu, t0, 1));
        t0 = fmaxf(t0, __shfl_xor_sync(0xffffffffu, t0, 2));
        t1 = fmaxf(t1, __shfl_xor_sync(0xffffffffu, t1, 1));
        t1 = fmaxf(t1, __shfl_xor_sync(0xffffffffu, t1, 2));
        float nm0 = fmaxf(m0, t0), nm1 = fmaxf(m1, t1);
        float al0 = __expf(m0 - nm0), al1 = __expf(m1 - nm1);
        float rs0 = 0.0f, rs1 = 0.0f;
#pragma unroll
        for (int ni = 0; ni < 16; ni++) {
            sacc[ni][0] = __expf(sacc[ni][0] - nm0);
            sacc[ni][1] = __expf(sacc[ni][1] - nm0);
            sacc[ni][2] = __expf(sacc[ni][2] - nm1);
            sacc[ni][3] = __expf(sacc[ni][3] - nm1);
            rs0 += sacc[ni][0] + sacc[ni][1];
            rs1 += sacc[ni][2] + sacc[ni][3];
        }
        rs0 += __shfl_xor_sync(0xffffffffu, rs0, 1);
        rs0 += __shfl_xor_sync(0xffffffffu, rs0, 2);
        rs1 += __shfl_xor_sync(0xffffffffu, rs1, 1);
        rs1 += __shfl_xor_sync(0xffffffffu, rs1, 2);
        l0 = l0 * al0 + rs0;
        l1 = l1 * al1 + rs1;
        m0 = nm0; m1 = nm1;
#pragma unroll
        for (int nj = 0; nj < 8; nj++) {
            oacc[nj][0] *= al0; oacc[nj][1] *= al0;
            oacc[nj][2] *= al1; oacc[nj][3] *= al1;
        }

#pragma unroll
        for (int kp = 0; kp < 8; kp++) {
            uint32_t pa_h[4], pa_l[4];
            split2(sacc[2 * kp][0],     sacc[2 * kp][1],     pa_h[0], pa_l[0]);
            split2(sacc[2 * kp][2],     sacc[2 * kp][3],     pa_h[1], pa_l[1]);
            split2(sacc[2 * kp + 1][0], sacc[2 * kp + 1][1], pa_h[2], pa_l[2]);
            split2(sacc[2 * kp + 1][2], sacc[2 * kp + 1][3], pa_h[3], pa_l[3]);
#pragma unroll
            for (int njp = 0; njp < 4; njp++) {
                uint32_t vbh[4], vbl[4];
                LDSM_X4(vbh[0], vbh[1], vbh[2], vbh[3],
                        smem_u32(&vh[(njp * 16 + kb_row) * V_STRIDE + kp * 16 + kb_kc]));
                LDSM_X4(vbl[0], vbl[1], vbl[2], vbl[3],
                        smem_u32(&vl[(njp * 16 + kb_row) * V_STRIDE + kp * 16 + kb_kc]));
                MMA_BF16(oacc[2 * njp],     pa_h, (vbh));
                MMA_BF16(oacc[2 * njp],     pa_h, (vbl));
                MMA_BF16(oacc[2 * njp],     pa_l, (vbh));
                MMA_BF16(oacc[2 * njp + 1], pa_h, (vbh + 2));
                MMA_BF16(oacc[2 * njp + 1], pa_h, (vbl + 2));
                MMA_BF16(oacc[2 * njp + 1], pa_l, (vbh + 2));
            }
        }
    }

    // ---- epilogue: normalize + write bf16 hi/lo ----
    float inv0 = 1.0f / l0, inv1 = 1.0f / l1;
    const int row0 = qt * 128 + wq * 16 + (lane >> 2);
    size_t ob = (size_t)(b * L + row0) * D + h * HD + (lane & 3) * 2;
#pragma unroll
    for (int nj = 0; nj < 8; nj++) {
        uint32_t hh, ll;
        split2(oacc[nj][0] * inv0, oacc[nj][1] * inv0, hh, ll);
        *(uint32_t*)&g_at_h[ob + nj * 8] = hh;
        *(uint32_t*)&g_at_l[ob + nj * 8] = ll;
        split2(oacc[nj][2] * inv1, oacc[nj][3] * inv1, hh, ll);
        *(uint32_t*)&g_at_h[ob + 8 * D + nj * 8] = hh;
        *(uint32_t*)&g_at_l[ob + 8 * D + nj * 8] = ll;
    }
}

// ---------------- time embedding projection --------------------------------
__global__ void time_proj_kernel(const float* __restrict__ te,
                                 const float* __restrict__ Wt,
                                 const float* __restrict__ bt) {
    __shared__ float s[D];
    int b   = blockIdx.y;
    int tid = threadIdx.x;
    for (int i = tid; i < D; i += 256) {
        float v = te[b * D + i];
        s[i] = v / (1.0f + expf(-v));
    }
    __syncthreads();
    int j = blockIdx.x * 256 + tid;
    float acc = bt[j];
#pragma unroll 8
    for (int k = 0; k < D; k++) acc = fmaf(s[k], Wt[(size_t)k * (6 * D) + j], acc);
    g_tp[b * 6 * D + j] = acc;
}

// ---------------- LayerNorm + AdaLN modulation -> bf16 hi/lo ----------------
__global__ void ln_mod_kernel(const float* __restrict__ x,
                              const float* __restrict__ g,
                              const float* __restrict__ be,
                              __nv_bfloat16* __restrict__ outh,
                              __nv_bfloat16* __restrict__ outl,
                              int shift_off, int scale_off) {
    int row = blockIdx.x;
    int b   = row / L;
    const float* xr = x + (size_t)row * D;
    int tid = threadIdx.x;
    float4 v = ((const float4*)xr)[tid];
    float s = v.x + v.y + v.z + v.w;
    float q = v.x * v.x + v.y * v.y + v.z * v.z + v.w * v.w;
#pragma unroll
    for (int o = 16; o; o >>= 1) {
        s += __shfl_xor_sync(0xffffffffu, s, o);
        q += __shfl_xor_sync(0xffffffffu, q, o);
    }
    __shared__ float ss[8], sq[8];
    __shared__ float s_mu, s_rs;
    int w = tid >> 5;
    if ((tid & 31) == 0) { ss[w] = s; sq[w] = q; }
    __syncthreads();
    if (tid == 0) {
        float S = 0.f, Q = 0.f;
        for (int i = 0; i < 8; i++) { S += ss[i]; Q += sq[i]; }
        float mu  = S / D;
        float var = Q / D - mu * mu;
        s_mu = mu;
        s_rs = rsqrtf(var + 1e-5f);
    }
    __syncthreads();
    float mu = s_mu, rs = s_rs;
    int j = tid * 4;
    const float* tpb = g_tp + b * 6 * D;
    float4 gv = ((const float4*)g)[tid];
    float4 bv = ((const float4*)be)[tid];
    float4 sc = *(const float4*)(tpb + scale_off + j);
    float4 sh = *(const float4*)(tpb + shift_off + j);
    float4 o;
    o.x = ((v.x - mu) * rs * gv.x + bv.x) * (1.0f + sc.x) + sh.x;
    o.y = ((v.y - mu) * rs * gv.y + bv.y) * (1.0f + sc.y) + sh.y;
    o.z = ((v.z - mu) * rs * gv.z + bv.z) * (1.0f + sc.z) + sh.z;
    o.w = ((v.w - mu) * rs * gv.w + bv.w) * (1.0f + sc.w) + sh.w;
    uint32_t h0, l0, h1, l1;
    split2(o.x, o.y, h0, l0);
    split2(o.z, o.w, h1, l1);
    *(uint2*)&outh[(size_t)row * D + j] = make_uint2(h0, h1);
    *(uint2*)&outl[(size_t)row * D + j] = make_uint2(l0, l1);
}

// ---------------- launch ------------------------------------------------------
extern "C" void kernel_launch(void* const* d_in, const int* in_sizes, int n_in,
                              void* d_out, int out_size) {
    const float* x     = (const float*)d_in[0];
    const float* te    = (const float*)d_in[1];
    const float* Wqkv  = (const float*)d_in[2];
    const float* bqkv  = (const float*)d_in[3];
    const float* Wproj = (const float*)d_in[4];
    const float* bproj = (const float*)d_in[5];
    const float* W1    = (const float*)d_in[6];
    const float* b1    = (const float*)d_in[7];
    const float* W2    = (const float*)d_in[8];
    const float* b2    = (const float*)d_in[9];
    const float* Wt    = (const float*)d_in[10];
    const float* bt    = (const float*)d_in[11];
    const float* g1    = (const float*)d_in[12];
    const float* be1   = (const float*)d_in[13];
    const float* g2    = (const float*)d_in[14];
    const float* be2   = (const float*)d_in[15];
    float* out = (float*)d_out;

    float *p_x1;
    __nv_bfloat16 *p_h_h, *p_h_l, *p_at_h, *p_at_l, *p_mlp_h, *p_mlp_l;
    __nv_bfloat16 *p_wqkv_h, *p_wqkv_l, *p_wproj_h, *p_wproj_l;
    __nv_bfloat16 *p_w1_h, *p_w1_l, *p_w2_h, *p_w2_l;
    cudaGetSymbolAddress((void**)&p_x1, g_x1);
    cudaGetSymbolAddress((void**)&p_h_h, g_h_h);
    cudaGetSymbolAddress((void**)&p_h_l, g_h_l);
    cudaGetSymbolAddress((void**)&p_at_h, g_at_h);
    cudaGetSymbolAddress((void**)&p_at_l, g_at_l);
    cudaGetSymbolAddress((void**)&p_mlp_h, g_mlp_h);
    cudaGetSymbolAddress((void**)&p_mlp_l, g_mlp_l);
    cudaGetSymbolAddress((void**)&p_wqkv_h, g_wqkv_h);
    cudaGetSymbolAddress((void**)&p_wqkv_l, g_wqkv_l);
    cudaGetSymbolAddress((void**)&p_wproj_h, g_wproj_h);
    cudaGetSymbolAddress((void**)&p_wproj_l, g_wproj_l);
    cudaGetSymbolAddress((void**)&p_w1_h, g_w1_h);
    cudaGetSymbolAddress((void**)&p_w1_l, g_w1_l);
    cudaGetSymbolAddress((void**)&p_w2_h, g_w2_h);
    cudaGetSymbolAddress((void**)&p_w2_l, g_w2_l);

    cudaFuncSetAttribute(flash_attn_kernel,
                         cudaFuncAttributeMaxDynamicSharedMemorySize, FA_SMEM);
    cudaFuncSetAttribute(hgemm<0, 0>, cudaFuncAttributeMaxDynamicSharedMemorySize, GT_SMEM);
    cudaFuncSetAttribute(hgemm<1, 1>, cudaFuncAttributeMaxDynamicSharedMemorySize, GT_SMEM);
    cudaFuncSetAttribute(hgemm<2, 0>, cudaFuncAttributeMaxDynamicSharedMemorySize, GT_SMEM);

    float* p_qkv;
    cudaGetSymbolAddress((void**)&p_qkv, g_qkv);

    // 0. weight convert + transpose (once per launch)
    wconv_kernel<<<dim3(3 * D / 32, D / 32), 256>>>(Wqkv, p_wqkv_h, p_wqkv_l, D, 3 * D);
    wconv_kernel<<<dim3(D / 32, D / 32), 256>>>(Wproj, p_wproj_h, p_wproj_l, D, D);
    wconv_kernel<<<dim3(MLP / 32, D / 32), 256>>>(W1, p_w1_h, p_w1_l, D, MLP);
    wconv_kernel<<<dim3(D / 32, MLP / 32), 256>>>(W2, p_w2_h, p_w2_l, MLP, D);
    // 1. time modulation params
    time_proj_kernel<<<dim3(6 * D / 256, NB), 256>>>(te, Wt, bt);
    // 2. LN1 + msa modulation -> h (bf16 hi/lo)
    ln_mod_kernel<<<ROWS, 256>>>(x, g1, be1, p_h_h, p_h_l, 0, D);
    // 3. QKV projection
    hgemm<0, 0><<<dim3(3 * D / 128, ROWS / 128), 256, GT_SMEM>>>(
        p_h_h, p_h_l, p_wqkv_h, p_wqkv_l, bqkv, nullptr, 0,
        p_qkv, nullptr, nullptr, 3 * D, D);
    // 4. fused flash attention -> attno (bf16 hi/lo)
    flash_attn_kernel<<<dim3(L / 128, NB * H), 256, FA_SMEM>>>();
    // 5. output projection + gated residual -> x1 (fp32)
    hgemm<2, 0><<<dim3(D / 128, ROWS / 128), 256, GT_SMEM>>>(
        p_at_h, p_at_l, p_wproj_h, p_wproj_l, bproj, x, 2 * D,
        p_x1, nullptr, nullptr, D, D);
    // 6. LN2 + mlp modulation -> h (bf16 hi/lo)
    ln_mod_kernel<<<ROWS, 256>>>(p_x1, g2, be2, p_h_h, p_h_l, 3 * D, 4 * D);
    // 7. MLP up + exact GELU -> mlp (bf16 hi/lo)
    hgemm<1, 1><<<dim3(MLP / 128, ROWS / 128), 256, GT_SMEM>>>(
        p_h_h, p_h_l, p_w1_h, p_w1_l, b1, nullptr, 0,
        nullptr, p_mlp_h, p_mlp_l, MLP, D);
    // 8. MLP down + gated residual -> output (fp32)
    hgemm<2, 0><<<dim3(D / 128, ROWS / 128), 256, GT_SMEM>>>(
        p_mlp_h, p_mlp_l, p_w2_h, p_w2_l, b2, p_x1, 5 * D,
        out, nullptr, nullptr, D, MLP);
}

// round 6
// speedup vs baseline: 3.0842x; 1.0630x over previous
#include <cuda_runtime.h>
#include <cuda_bf16.h>
#include <math.h>
#include <stdint.h>

// Problem constants
constexpr int D    = 1024;
constexpr int NB   = 4;
constexpr int L    = 2048;
constexpr int H    = 16;
constexpr int HD   = 64;
constexpr int MLP  = 4096;
constexpr int ROWS = NB * L;  // 8192

// ---------------- scratch (device globals; no allocation allowed) ----------
__device__ float g_tp[NB * 6 * D];
__device__ float g_x1[(size_t)ROWS * D];
// bf16 hi/lo activation buffers
__device__ __nv_bfloat16 g_h_h[(size_t)ROWS * D];
__device__ __nv_bfloat16 g_h_l[(size_t)ROWS * D];
__device__ __nv_bfloat16 g_at_h[(size_t)ROWS * D];
__device__ __nv_bfloat16 g_at_l[(size_t)ROWS * D];
__device__ __nv_bfloat16 g_mlp_h[(size_t)ROWS * MLP];
__device__ __nv_bfloat16 g_mlp_l[(size_t)ROWS * MLP];
// attention operands, head-major: q/k [bh][L][HD], vt [bh][HD][L]
__device__ __nv_bfloat16 g_q_h[(size_t)ROWS * D];
__device__ __nv_bfloat16 g_q_l[(size_t)ROWS * D];
__device__ __nv_bfloat16 g_k_h[(size_t)ROWS * D];
__device__ __nv_bfloat16 g_k_l[(size_t)ROWS * D];
__device__ __nv_bfloat16 g_vt_h[(size_t)ROWS * D];
__device__ __nv_bfloat16 g_vt_l[(size_t)ROWS * D];
// bf16 hi/lo transposed weights [N][K]
__device__ __nv_bfloat16 g_wqkv_h[3 * D * D];
__device__ __nv_bfloat16 g_wqkv_l[3 * D * D];
__device__ __nv_bfloat16 g_wproj_h[D * D];
__device__ __nv_bfloat16 g_wproj_l[D * D];
__device__ __nv_bfloat16 g_w1_h[D * MLP];
__device__ __nv_bfloat16 g_w1_l[D * MLP];
__device__ __nv_bfloat16 g_w2_h[MLP * D];
__device__ __nv_bfloat16 g_w2_l[MLP * D];

// =================== helpers ==========================
__device__ __forceinline__ uint32_t smem_u32(const void* p) {
    uint32_t a;
    asm("{ .reg .u64 t; cvta.to.shared.u64 t, %1; cvt.u32.u64 %0, t; }"
        : "=r"(a) : "l"(p));
    return a;
}
__device__ __forceinline__ void split2(float x, float y, uint32_t& hi, uint32_t& lo) {
    __nv_bfloat162 h = __floats2bfloat162_rn(x, y);
    float rx = __bfloat162float(h.x), ry = __bfloat162float(h.y);
    __nv_bfloat162 l = __floats2bfloat162_rn(x - rx, y - ry);
    hi = *reinterpret_cast<uint32_t*>(&h);
    lo = *reinterpret_cast<uint32_t*>(&l);
}
__device__ __forceinline__ void cp16(uint32_t saddr, const void* g) {
    asm volatile("cp.async.cg.shared.global [%0], [%1], 16;" :: "r"(saddr), "l"(g));
}
#define CP_COMMIT() asm volatile("cp.async.commit_group;" ::: "memory")
#define CP_WAIT(n)  asm volatile("cp.async.wait_group %0;" :: "n"(n) : "memory")

#define LDSM_X4(r0, r1, r2, r3, addr)                                          \
    asm volatile("ldmatrix.sync.aligned.m8n8.x4.shared.b16 {%0,%1,%2,%3}, [%4];" \
                 : "=r"(r0), "=r"(r1), "=r"(r2), "=r"(r3) : "r"(addr))
#define LDSM_X2(r0, r1, addr)                                                  \
    asm volatile("ldmatrix.sync.aligned.m8n8.x2.shared.b16 {%0,%1}, [%2];"     \
                 : "=r"(r0), "=r"(r1) : "r"(addr))
#define MMA_BF16(c, a, b)                                                      \
    asm volatile("mma.sync.aligned.m16n8k16.row.col.f32.bf16.bf16.f32 "        \
                 "{%0,%1,%2,%3}, {%4,%5,%6,%7}, {%8,%9}, {%0,%1,%2,%3};"       \
                 : "+f"((c)[0]), "+f"((c)[1]), "+f"((c)[2]), "+f"((c)[3])      \
                 : "r"((a)[0]), "r"((a)[1]), "r"((a)[2]), "r"((a)[3]),         \
                   "r"((b)[0]), "r"((b)[1]))

// ============ weight convert+transpose: W[K][N] f32 -> Wh/Wl[N][K] bf16 ====
__global__ void wconv_kernel(const float* __restrict__ W,
                             __nv_bfloat16* __restrict__ Wh,
                             __nv_bfloat16* __restrict__ Wl, int K, int N) {
    __shared__ float s[32][33];
    const int tid = threadIdx.x;
    const int tx = tid & 31, ty = tid >> 5;
    const int n0 = blockIdx.x * 32, k0 = blockIdx.y * 32;
#pragma unroll
    for (int p = 0; p < 4; p++)
        s[ty + 8 * p][tx] = W[(size_t)(k0 + ty + 8 * p) * N + n0 + tx];
    __syncthreads();
#pragma unroll
    for (int p = 0; p < 4; p++) {
        float v = s[tx][ty + 8 * p];
        __nv_bfloat16 h = __float2bfloat16(v);
        __nv_bfloat16 l = __float2bfloat16(v - __bfloat162float(h));
        size_t o = (size_t)(n0 + ty + 8 * p) * K + k0 + tx;
        Wh[o] = h;
        Wl[o] = l;
    }
}

// ================== HMMA GEMM: bf16 hi/lo in, cp.async pipeline =============
// EPI 0: bias. EPI 1: exact GELU. EPI 2: res + gate*(acc+bias).
// OUTK 0: fp32 C. OUTK 1: bf16 hi/lo Ch/Cl. OUTK 2: QKV scatter (q/k/vt bufs).
constexpr int GT_ROWB  = 80;
constexpr int GT_TILE  = 128 * GT_ROWB;
constexpr int GT_STAGE = 4 * GT_TILE;
constexpr int GT_SMEM  = 2 * GT_STAGE;  // 81920 B

template <int EPI, int OUTK>
__global__ void __launch_bounds__(256, 2) hgemm(
    const __nv_bfloat16* __restrict__ Ah, const __nv_bfloat16* __restrict__ Al,
    const __nv_bfloat16* __restrict__ Bh, const __nv_bfloat16* __restrict__ Bl,
    const float* __restrict__ bias, const float* __restrict__ res, int gate_off,
    float* __restrict__ C, __nv_bfloat16* __restrict__ Ch,
    __nv_bfloat16* __restrict__ Cl, int N, int K) {
    extern __shared__ char smem[];
    const uint32_t sbase = smem_u32(smem);
    const int tid  = threadIdx.x;
    const int lane = tid & 31;
    const int warp = tid >> 5;
    const int wm   = warp >> 1;
    const int wn   = warp & 1;
    const int m_base = blockIdx.y * 128;
    const int n_base = blockIdx.x * 128;

    const int c0r = tid >> 2, c0c = tid & 3;
    const int c1r = (tid + 256) >> 2, c1c = c0c;
    const __nv_bfloat16* srcs[4] = {Ah + (size_t)m_base * K, Al + (size_t)m_base * K,
                                    Bh + (size_t)n_base * K, Bl + (size_t)n_base * K};

    auto load_stage = [&](int stage, int k0) {
        uint32_t sb = sbase + stage * GT_STAGE;
#pragma unroll
        for (int t = 0; t < 4; t++) {
            const __nv_bfloat16* g = srcs[t] + k0;
            cp16(sb + t * GT_TILE + c0r * GT_ROWB + c0c * 16,
                 g + (size_t)c0r * K + c0c * 8);
            cp16(sb + t * GT_TILE + c1r * GT_ROWB + c1c * 16,
                 g + (size_t)c1r * K + c1c * 8);
        }
    };

    float acc[2][8][4];
#pragma unroll
    for (int mi = 0; mi < 2; mi++)
#pragma unroll
        for (int ni = 0; ni < 8; ni++)
#pragma unroll
            for (int c = 0; c < 4; c++) acc[mi][ni][c] = 0.0f;

    const int a_row = lane & 15;
    const int a_kc  = (lane >> 4) * 8;
    const int b_row = lane & 7;
    const int b_kc  = ((lane >> 3) & 1) * 8;

    const int nblk = K >> 5;
    load_stage(0, 0);
    CP_COMMIT();
    load_stage(1, 32);
    CP_COMMIT();

    for (int blk = 0; blk < nblk; blk++) {
        if (blk == nblk - 1) CP_WAIT(0); else CP_WAIT(1);
        __syncthreads();
        const uint32_t sb = sbase + (blk & 1) * GT_STAGE;
        const uint32_t s_ah = sb;
        const uint32_t s_al = sb + GT_TILE;
        const uint32_t s_bh = sb + 2 * GT_TILE;
        const uint32_t s_bl = sb + 3 * GT_TILE;
#pragma unroll
        for (int ks = 0; ks < 2; ks++) {
            const int kc = ks * 16;
            uint32_t a_h[2][4], a_l[2][4];
#pragma unroll
            for (int mi = 0; mi < 2; mi++) {
                uint32_t ra = (wm * 32 + mi * 16 + a_row) * GT_ROWB + (kc + a_kc) * 2;
                LDSM_X4(a_h[mi][0], a_h[mi][1], a_h[mi][2], a_h[mi][3], s_ah + ra);
                LDSM_X4(a_l[mi][0], a_l[mi][1], a_l[mi][2], a_l[mi][3], s_al + ra);
            }
#pragma unroll
            for (int ni = 0; ni < 8; ni++) {
                uint32_t rb = (wn * 64 + ni * 8 + b_row) * GT_ROWB + (kc + b_kc) * 2;
                uint32_t b_h[2], b_l[2];
                LDSM_X2(b_h[0], b_h[1], s_bh + rb);
                LDSM_X2(b_l[0], b_l[1], s_bl + rb);
#pragma unroll
                for (int mi = 0; mi < 2; mi++) {
                    MMA_BF16(acc[mi][ni], a_h[mi], b_h);
                    MMA_BF16(acc[mi][ni], a_h[mi], b_l);
                    MMA_BF16(acc[mi][ni], a_l[mi], b_h);
                }
            }
        }
        __syncthreads();
        if (blk + 2 < nblk) {
            load_stage(blk & 1, (blk + 2) << 5);
            CP_COMMIT();
        }
    }

    // ---- epilogue ----
    const int col_base = n_base + wn * 64 + (lane & 3) * 2;
    const int row_base = m_base + wm * 32 + (lane >> 2);
#pragma unroll
    for (int mi = 0; mi < 2; mi++) {
#pragma unroll
        for (int half = 0; half < 2; half++) {
            const int m = row_base + mi * 16 + half * 8;
            const int bb = m >> 11;  // m / L
#pragma unroll
            for (int ni = 0; ni < 8; ni++) {
                const int col = col_base + ni * 8;
                float2 bv = *(const float2*)(bias + col);
                float vx = acc[mi][ni][half * 2 + 0] + bv.x;
                float vy = acc[mi][ni][half * 2 + 1] + bv.y;
                if (EPI == 1) {
                    vx = 0.5f * vx * (1.0f + erff(vx * 0.7071067811865475f));
                    vy = 0.5f * vy * (1.0f + erff(vy * 0.7071067811865475f));
                }
                if (EPI == 2) {
                    float2 gv = *(const float2*)(g_tp + bb * 6 * D + gate_off + col);
                    float2 rv = *(const float2*)(res + (size_t)m * N + col);
                    vx = rv.x + gv.x * vx;
                    vy = rv.y + gv.y * vy;
                }
                if (OUTK == 0) {
                    *(float2*)(C + (size_t)m * N + col) = make_float2(vx, vy);
                } else if (OUTK == 1) {
                    uint32_t hh, ll;
                    split2(vx, vy, hh, ll);
                    *(uint32_t*)&Ch[(size_t)m * N + col] = hh;
                    *(uint32_t*)&Cl[(size_t)m * N + col] = ll;
                } else {
                    // QKV scatter: part 0=Q (scaled 2^-3), 1=K, 2=V transposed
                    const int part = col >> 10;
                    const int hh_ = (col & 1023) >> 6;
                    const int hd  = col & 63;
                    const int tok = m & (L - 1);
                    const size_t bh = (size_t)(bb * H + hh_);
                    if (part == 0) {
                        uint32_t hi, lo;
                        split2(vx * 0.125f, vy * 0.125f, hi, lo);
                        size_t o = (bh * L + tok) * HD + hd;
                        *(uint32_t*)&g_q_h[o] = hi;
                        *(uint32_t*)&g_q_l[o] = lo;
                    } else if (part == 1) {
                        uint32_t hi, lo;
                        split2(vx, vy, hi, lo);
                        size_t o = (bh * L + tok) * HD + hd;
                        *(uint32_t*)&g_k_h[o] = hi;
                        *(uint32_t*)&g_k_l[o] = lo;
                    } else {
                        uint32_t hi, lo;
                        split2(vx, vy, hi, lo);
                        __nv_bfloat162 hv = *reinterpret_cast<__nv_bfloat162*>(&hi);
                        __nv_bfloat162 lv = *reinterpret_cast<__nv_bfloat162*>(&lo);
                        size_t o = (bh * HD + hd) * L + tok;
                        g_vt_h[o]     = hv.x;
                        g_vt_h[o + L] = hv.y;
                        g_vt_l[o]     = lv.x;
                        g_vt_l[o + L] = lv.y;
                    }
                }
            }
        }
    }
}

// ================== fused flash attention v2: cp.async pipelined ============
constexpr int QK_STRIDE = 72;                 // bf16 elems (144 B row)
constexpr int V_STRIDE  = 136;                // bf16 elems (272 B row)
constexpr int FA_QEL    = 128 * QK_STRIDE;    // 9216
constexpr int FA_KEL    = 128 * QK_STRIDE;    // 9216
constexpr int FA_VEL    = 64 * V_STRIDE;      // 8704
constexpr int FA_STAGEEL = 2 * FA_KEL + 2 * FA_VEL;  // 35840
constexpr int FA_SMEM   = (2 * FA_QEL + 2 * FA_STAGEEL) * 2;  // 180224 B

__global__ void __launch_bounds__(256, 1) flash_attn_kernel() {
    extern __shared__ __nv_bfloat16 fs[];
    const uint32_t sbase = smem_u32(fs);
    __nv_bfloat16* qh = fs;
    __nv_bfloat16* ql = fs + FA_QEL;

    const int tid  = threadIdx.x;
    const int lane = tid & 31;
    const int wq   = tid >> 5;
    const int qt   = blockIdx.x;
    const int bh   = blockIdx.y;

    const __nv_bfloat16* gq_h = g_q_h + ((size_t)bh * L + qt * 128) * HD;
    const __nv_bfloat16* gq_l = g_q_l + ((size_t)bh * L + qt * 128) * HD;
    const __nv_bfloat16* gk_h = g_k_h + (size_t)bh * L * HD;
    const __nv_bfloat16* gk_l = g_k_l + (size_t)bh * L * HD;
    const __nv_bfloat16* gv_h = g_vt_h + (size_t)bh * HD * L;
    const __nv_bfloat16* gv_l = g_vt_l + (size_t)bh * HD * L;

    auto load_kv = [&](int kt, int s) {
        uint32_t sb = sbase + (2 * FA_QEL + s * FA_STAGEEL) * 2;
        const __nv_bfloat16* kh_g = gk_h + (size_t)(kt * 128) * HD;
        const __nv_bfloat16* kl_g = gk_l + (size_t)(kt * 128) * HD;
#pragma unroll
        for (int i = 0; i < 4; i++) {
            int c = tid + 256 * i;
            int row = c >> 3, col = c & 7;
            cp16(sb + row * 144 + col * 16, kh_g + (size_t)row * HD + col * 8);
            cp16(sb + FA_KEL * 2 + row * 144 + col * 16, kl_g + (size_t)row * HD + col * 8);
        }
        uint32_t vb = sb + 4 * FA_KEL;  // bytes: 2*FA_KEL elems * 2
#pragma unroll
        for (int i = 0; i < 4; i++) {
            int c = tid + 256 * i;
            int row = c >> 4, col = c & 15;
            cp16(vb + row * 272 + col * 16, gv_h + (size_t)row * L + kt * 128 + col * 8);
            cp16(vb + FA_VEL * 2 + row * 272 + col * 16,
                 gv_l + (size_t)row * L + kt * 128 + col * 8);
        }
    };

    // prologue: Q + stage 0
#pragma unroll
    for (int i = 0; i < 4; i++) {
        int c = tid + 256 * i;
        int row = c >> 3, col = c & 7;
        cp16(sbase + row * 144 + col * 16, gq_h + (size_t)row * HD + col * 8);
        cp16(sbase + FA_QEL * 2 + row * 144 + col * 16, gq_l + (size_t)row * HD + col * 8);
    }
    load_kv(0, 0);
    CP_COMMIT();
    CP_WAIT(0);
    __syncthreads();

    // Q fragments (persist)
    const int a_row = lane & 15;
    const int a_kc  = (lane >> 4) * 8;
    uint32_t qa_h[4][4], qa_l[4][4];
#pragma unroll
    for (int ks = 0; ks < 4; ks++) {
        LDSM_X4(qa_h[ks][0], qa_h[ks][1], qa_h[ks][2], qa_h[ks][3],
                smem_u32(&qh[(wq * 16 + a_row) * QK_STRIDE + ks * 16 + a_kc]));
        LDSM_X4(qa_l[ks][0], qa_l[ks][1], qa_l[ks][2], qa_l[ks][3],
                smem_u32(&ql[(wq * 16 + a_row) * QK_STRIDE + ks * 16 + a_kc]));
    }

    const int kb_row = (lane >> 4) * 8 + (lane & 7);
    const int kb_kc  = ((lane >> 3) & 1) * 8;

    float oacc[8][4];
#pragma unroll
    for (int nj = 0; nj < 8; nj++)
#pragma unroll
        for (int c = 0; c < 4; c++) oacc[nj][c] = 0.0f;
    float m0 = -INFINITY, m1 = -INFINITY, l0 = 0.0f, l1 = 0.0f;

    constexpr int NT = L / 128;
    for (int kt = 0; kt < NT; kt++) {
        if (kt + 1 < NT) {
            load_kv(kt + 1, (kt + 1) & 1);
            CP_COMMIT();
        }
        __nv_bfloat16* st = fs + 2 * FA_QEL + (kt & 1) * FA_STAGEEL;
        __nv_bfloat16* kh = st;
        __nv_bfloat16* kl = st + FA_KEL;
        __nv_bfloat16* vh = st + 2 * FA_KEL;
        __nv_bfloat16* vl = st + 2 * FA_KEL + FA_VEL;

        // ---- S = Q K^T ----
        float sacc[16][4];
#pragma unroll
        for (int ni = 0; ni < 16; ni++)
#pragma unroll
            for (int c = 0; c < 4; c++) sacc[ni][c] = 0.0f;
#pragma unroll
        for (int ks = 0; ks < 4; ks++) {
#pragma unroll
            for (int nip = 0; nip < 8; nip++) {
                uint32_t bh_[4], bl_[4];
                LDSM_X4(bh_[0], bh_[1], bh_[2], bh_[3],
                        smem_u32(&kh[(nip * 16 + kb_row) * QK_STRIDE + ks * 16 + kb_kc]));
                LDSM_X4(bl_[0], bl_[1], bl_[2], bl_[3],
                        smem_u32(&kl[(nip * 16 + kb_row) * QK_STRIDE + ks * 16 + kb_kc]));
                MMA_BF16(sacc[2 * nip],     qa_h[ks], (bh_));
                MMA_BF16(sacc[2 * nip],     qa_h[ks], (bl_));
                MMA_BF16(sacc[2 * nip],     qa_l[ks], (bh_));
                MMA_BF16(sacc[2 * nip + 1], qa_h[ks], (bh_ + 2));
                MMA_BF16(sacc[2 * nip + 1], qa_h[ks], (bl_ + 2));
                MMA_BF16(sacc[2 * nip + 1], qa_l[ks], (bh_ + 2));
            }
        }

        // ---- online softmax ----
        float t0 = -INFINITY, t1 = -INFINITY;
#pragma unroll
        for (int ni = 0; ni < 16; ni++) {
            t0 = fmaxf(t0, fmaxf(sacc[ni][0], sacc[ni][1]));
            t1 = fmaxf(t1, fmaxf(sacc[ni][2], sacc[ni][3]));
        }
        t0 = fmaxf(t0, __shfl_xor_sync(0xffffffffu, t0, 1));
        t0 = fmaxf(t0, __shfl_xor_sync(0xffffffffu, t0, 2));
        t1 = fmaxf(t1, __shfl_xor_sync(0xffffffffu, t1, 1));
        t1 = fmaxf(t1, __shfl_xor_sync(0xffffffffu, t1, 2));
        float nm0 = fmaxf(m0, t0), nm1 = fmaxf(m1, t1);
        float al0 = __expf(m0 - nm0), al1 = __expf(m1 - nm1);
        float rs0 = 0.0f, rs1 = 0.0f;
#pragma unroll
        for (int ni = 0; ni < 16; ni++) {
            sacc[ni][0] = __expf(sacc[ni][0] - nm0);
            sacc[ni][1] = __expf(sacc[ni][1] - nm0);
            sacc[ni][2] = __expf(sacc[ni][2] - nm1);
            sacc[ni][3] = __expf(sacc[ni][3] - nm1);
            rs0 += sacc[ni][0] + sacc[ni][1];
            rs1 += sacc[ni][2] + sacc[ni][3];
        }
        rs0 += __shfl_xor_sync(0xffffffffu, rs0, 1);
        rs0 += __shfl_xor_sync(0xffffffffu, rs0, 2);
        rs1 += __shfl_xor_sync(0xffffffffu, rs1, 1);
        rs1 += __shfl_xor_sync(0xffffffffu, rs1, 2);
        l0 = l0 * al0 + rs0;
        l1 = l1 * al1 + rs1;
        m0 = nm0; m1 = nm1;
#pragma unroll
        for (int nj = 0; nj < 8; nj++) {
            oacc[nj][0] *= al0; oacc[nj][1] *= al0;
            oacc[nj][2] *= al1; oacc[nj][3] *= al1;
        }

        // ---- O += P V ----
#pragma unroll
        for (int kp = 0; kp < 8; kp++) {
            uint32_t pa_h[4], pa_l[4];
            split2(sacc[2 * kp][0],     sacc[2 * kp][1],     pa_h[0], pa_l[0]);
            split2(sacc[2 * kp][2],     sacc[2 * kp][3],     pa_h[1], pa_l[1]);
            split2(sacc[2 * kp + 1][0], sacc[2 * kp + 1][1], pa_h[2], pa_l[2]);
            split2(sacc[2 * kp + 1][2], sacc[2 * kp + 1][3], pa_h[3], pa_l[3]);
#pragma unroll
            for (int njp = 0; njp < 4; njp++) {
                uint32_t vbh[4], vbl[4];
                LDSM_X4(vbh[0], vbh[1], vbh[2], vbh[3],
                        smem_u32(&vh[(njp * 16 + kb_row) * V_STRIDE + kp * 16 + kb_kc]));
                LDSM_X4(vbl[0], vbl[1], vbl[2], vbl[3],
                        smem_u32(&vl[(njp * 16 + kb_row) * V_STRIDE + kp * 16 + kb_kc]));
                MMA_BF16(oacc[2 * njp],     pa_h, (vbh));
                MMA_BF16(oacc[2 * njp],     pa_h, (vbl));
                MMA_BF16(oacc[2 * njp],     pa_l, (vbh));
                MMA_BF16(oacc[2 * njp + 1], pa_h, (vbh + 2));
                MMA_BF16(oacc[2 * njp + 1], pa_h, (vbl + 2));
                MMA_BF16(oacc[2 * njp + 1], pa_l, (vbh + 2));
            }
        }
        if (kt + 1 < NT) {
            CP_WAIT(0);
            __syncthreads();
        }
    }

    // ---- epilogue ----
    float inv0 = 1.0f / l0, inv1 = 1.0f / l1;
    const int b = bh >> 4, h = bh & 15;
    const int row0 = qt * 128 + wq * 16 + (lane >> 2);
    size_t ob = (size_t)(b * L + row0) * D + h * HD + (lane & 3) * 2;
#pragma unroll
    for (int nj = 0; nj < 8; nj++) {
        uint32_t hh, ll;
        split2(oacc[nj][0] * inv0, oacc[nj][1] * inv0, hh, ll);
        *(uint32_t*)&g_at_h[ob + nj * 8] = hh;
        *(uint32_t*)&g_at_l[ob + nj * 8] = ll;
        split2(oacc[nj][2] * inv1, oacc[nj][3] * inv1, hh, ll);
        *(uint32_t*)&g_at_h[ob + 8 * D + nj * 8] = hh;
        *(uint32_t*)&g_at_l[ob + 8 * D + nj * 8] = ll;
    }
}

// ---------------- time embedding projection --------------------------------
__global__ void time_proj_kernel(const float* __restrict__ te,
                                 const float* __restrict__ Wt,
                                 const float* __restrict__ bt) {
    __shared__ float s[D];
    int b   = blockIdx.y;
    int tid = threadIdx.x;
    for (int i = tid; i < D; i += 256) {
        float v = te[b * D + i];
        s[i] = v / (1.0f + expf(-v));
    }
    __syncthreads();
    int j = blockIdx.x * 256 + tid;
    float acc = bt[j];
#pragma unroll 8
    for (int k = 0; k < D; k++) acc = fmaf(s[k], Wt[(size_t)k * (6 * D) + j], acc);
    g_tp[b * 6 * D + j] = acc;
}

// ---------------- LayerNorm + AdaLN modulation -> bf16 hi/lo ----------------
__global__ void ln_mod_kernel(const float* __restrict__ x,
                              const float* __restrict__ g,
                              const float* __restrict__ be,
                              __nv_bfloat16* __restrict__ outh,
                              __nv_bfloat16* __restrict__ outl,
                              int shift_off, int scale_off) {
    int row = blockIdx.x;
    int b   = row / L;
    const float* xr = x + (size_t)row * D;
    int tid = threadIdx.x;
    float4 v = ((const float4*)xr)[tid];
    float s = v.x + v.y + v.z + v.w;
    float q = v.x * v.x + v.y * v.y + v.z * v.z + v.w * v.w;
#pragma unroll
    for (int o = 16; o; o >>= 1) {
        s += __shfl_xor_sync(0xffffffffu, s, o);
        q += __shfl_xor_sync(0xffffffffu, q, o);
    }
    __shared__ float ss[8], sq[8];
    __shared__ float s_mu, s_rs;
    int w = tid >> 5;
    if ((tid & 31) == 0) { ss[w] = s; sq[w] = q; }
    __syncthreads();
    if (tid == 0) {
        float S = 0.f, Q = 0.f;
        for (int i = 0; i < 8; i++) { S += ss[i]; Q += sq[i]; }
        float mu  = S / D;
        float var = Q / D - mu * mu;
        s_mu = mu;
        s_rs = rsqrtf(var + 1e-5f);
    }
    __syncthreads();
    float mu = s_mu, rs = s_rs;
    int j = tid * 4;
    const float* tpb = g_tp + b * 6 * D;
    float4 gv = ((const float4*)g)[tid];
    float4 bv = ((const float4*)be)[tid];
    float4 sc = *(const float4*)(tpb + scale_off + j);
    float4 sh = *(const float4*)(tpb + shift_off + j);
    float4 o;
    o.x = ((v.x - mu) * rs * gv.x + bv.x) * (1.0f + sc.x) + sh.x;
    o.y = ((v.y - mu) * rs * gv.y + bv.y) * (1.0f + sc.y) + sh.y;
    o.z = ((v.z - mu) * rs * gv.z + bv.z) * (1.0f + sc.z) + sh.z;
    o.w = ((v.w - mu) * rs * gv.w + bv.w) * (1.0f + sc.w) + sh.w;
    uint32_t h0, l0, h1, l1;
    split2(o.x, o.y, h0, l0);
    split2(o.z, o.w, h1, l1);
    *(uint2*)&outh[(size_t)row * D + j] = make_uint2(h0, h1);
    *(uint2*)&outl[(size_t)row * D + j] = make_uint2(l0, l1);
}

// ---------------- launch ------------------------------------------------------
extern "C" void kernel_launch(void* const* d_in, const int* in_sizes, int n_in,
                              void* d_out, int out_size) {
    const float* x     = (const float*)d_in[0];
    const float* te    = (const float*)d_in[1];
    const float* Wqkv  = (const float*)d_in[2];
    const float* bqkv  = (const float*)d_in[3];
    const float* Wproj = (const float*)d_in[4];
    const float* bproj = (const float*)d_in[5];
    const float* W1    = (const float*)d_in[6];
    const float* b1    = (const float*)d_in[7];
    const float* W2    = (const float*)d_in[8];
    const float* b2    = (const float*)d_in[9];
    const float* Wt    = (const float*)d_in[10];
    const float* bt    = (const float*)d_in[11];
    const float* g1    = (const float*)d_in[12];
    const float* be1   = (const float*)d_in[13];
    const float* g2    = (const float*)d_in[14];
    const float* be2   = (const float*)d_in[15];
    float* out = (float*)d_out;

    float *p_x1;
    __nv_bfloat16 *p_h_h, *p_h_l, *p_at_h, *p_at_l, *p_mlp_h, *p_mlp_l;
    __nv_bfloat16 *p_wqkv_h, *p_wqkv_l, *p_wproj_h, *p_wproj_l;
    __nv_bfloat16 *p_w1_h, *p_w1_l, *p_w2_h, *p_w2_l;
    cudaGetSymbolAddress((void**)&p_x1, g_x1);
    cudaGetSymbolAddress((void**)&p_h_h, g_h_h);
    cudaGetSymbolAddress((void**)&p_h_l, g_h_l);
    cudaGetSymbolAddress((void**)&p_at_h, g_at_h);
    cudaGetSymbolAddress((void**)&p_at_l, g_at_l);
    cudaGetSymbolAddress((void**)&p_mlp_h, g_mlp_h);
    cudaGetSymbolAddress((void**)&p_mlp_l, g_mlp_l);
    cudaGetSymbolAddress((void**)&p_wqkv_h, g_wqkv_h);
    cudaGetSymbolAddress((void**)&p_wqkv_l, g_wqkv_l);
    cudaGetSymbolAddress((void**)&p_wproj_h, g_wproj_h);
    cudaGetSymbolAddress((void**)&p_wproj_l, g_wproj_l);
    cudaGetSymbolAddress((void**)&p_w1_h, g_w1_h);
    cudaGetSymbolAddress((void**)&p_w1_l, g_w1_l);
    cudaGetSymbolAddress((void**)&p_w2_h, g_w2_h);
    cudaGetSymbolAddress((void**)&p_w2_l, g_w2_l);

    cudaFuncSetAttribute(flash_attn_kernel,
                         cudaFuncAttributeMaxDynamicSharedMemorySize, FA_SMEM);
    cudaFuncSetAttribute(hgemm<0, 2>, cudaFuncAttributeMaxDynamicSharedMemorySize, GT_SMEM);
    cudaFuncSetAttribute(hgemm<1, 1>, cudaFuncAttributeMaxDynamicSharedMemorySize, GT_SMEM);
    cudaFuncSetAttribute(hgemm<2, 0>, cudaFuncAttributeMaxDynamicSharedMemorySize, GT_SMEM);

    // 0. weight convert + transpose (once per launch)
    wconv_kernel<<<dim3(3 * D / 32, D / 32), 256>>>(Wqkv, p_wqkv_h, p_wqkv_l, D, 3 * D);
    wconv_kernel<<<dim3(D / 32, D / 32), 256>>>(Wproj, p_wproj_h, p_wproj_l, D, D);
    wconv_kernel<<<dim3(MLP / 32, D / 32), 256>>>(W1, p_w1_h, p_w1_l, D, MLP);
    wconv_kernel<<<dim3(D / 32, MLP / 32), 256>>>(W2, p_w2_h, p_w2_l, MLP, D);
    // 1. time modulation params
    time_proj_kernel<<<dim3(6 * D / 256, NB), 256>>>(te, Wt, bt);
    // 2. LN1 + msa modulation -> h (bf16 hi/lo)
    ln_mod_kernel<<<ROWS, 256>>>(x, g1, be1, p_h_h, p_h_l, 0, D);
    // 3. QKV projection -> head-major q/k + transposed v (bf16 hi/lo)
    hgemm<0, 2><<<dim3(3 * D / 128, ROWS / 128), 256, GT_SMEM>>>(
        p_h_h, p_h_l, p_wqkv_h, p_wqkv_l, bqkv, nullptr, 0,
        nullptr, nullptr, nullptr, 3 * D, D);
    // 4. fused flash attention -> attno (bf16 hi/lo)
    flash_attn_kernel<<<dim3(L / 128, NB * H), 256, FA_SMEM>>>();
    // 5. output projection + gated residual -> x1 (fp32)
    hgemm<2, 0><<<dim3(D / 128, ROWS / 128), 256, GT_SMEM>>>(
        p_at_h, p_at_l, p_wproj_h, p_wproj_l, bproj, x, 2 * D,
        p_x1, nullptr, nullptr, D, D);
    // 6. LN2 + mlp modulation -> h (bf16 hi/lo)
    ln_mod_kernel<<<ROWS, 256>>>(p_x1, g2, be2, p_h_h, p_h_l, 3 * D, 4 * D);
    // 7. MLP up + exact GELU -> mlp (bf16 hi/lo)
    hgemm<1, 1><<<dim3(MLP / 128, ROWS / 128), 256, GT_SMEM>>>(
        p_h_h, p_h_l, p_w1_h, p_w1_l, b1, nullptr, 0,
        nullptr, p_mlp_h, p_mlp_l, MLP, D);
    // 8. MLP down + gated residual -> output (fp32)
    hgemm<2, 0><<<dim3(D / 128, ROWS / 128), 256, GT_SMEM>>>(
        p_mlp_h, p_mlp_l, p_w2_h, p_w2_l, b2, p_x1, 5 * D,
        out, nullptr, nullptr, D, MLP);
}